// round 10
// baseline (speedup 1.0000x reference)
#include <cuda_runtime.h>
#include <cuda_fp16.h>
#include <cstdint>
#include <math.h>

// Problem constants
#define Bz 4
#define Sz 2048
#define Dz 1024
#define Hz 16
#define HDz 64
#define D3z 3072
#define Mz (Bz * Sz)

// Scratch (device globals: allocation-free per harness rules)
// fp16 buffers are K-pair-permuted: within each 16-element K-block, half2
// pairs are ordered [m0,m4,m1,m5,m2,m6,m3,m7] (m = pair (2m,2m+1)).
__device__ float    g_qkv[(size_t)Mz * D3z];      // [8192,3072] fp32
__device__ uint32_t g_attn[(size_t)Mz * Dz / 2];  // fp16, permuted
__device__ uint32_t g_x  [(size_t)Mz * Dz / 2];   // fp16, permuted
__device__ uint32_t g_wq [(size_t)D3z * Dz / 2];  // fp16, permuted
__device__ uint32_t g_wp [(size_t)Dz * Dz / 2];   // fp16, permuted

// ---------------------------------------------------------------------------
// Helpers
// ---------------------------------------------------------------------------
__device__ __forceinline__ uint32_t smem_u32(const void* p) {
    uint32_t a;
    asm("{ .reg .u64 t; cvta.to.shared.u64 t, %1; cvt.u32.u64 %0, t; }"
        : "=r"(a) : "l"(p));
    return a;
}

__device__ __forceinline__ uint32_t f2h2(float a, float b) {
    __half2 h = __floats2half2_rn(a, b);   // low 16 bits = a
    return *(uint32_t*)&h;
}

#define CP_ASYNC16(dst, src) \
    asm volatile("cp.async.cg.shared.global [%0], [%1], 16;" \
        :: "r"((uint32_t)(dst)), "l"(src) : "memory")
#define CP_COMMIT() asm volatile("cp.async.commit_group;" ::: "memory")
#define CP_WAIT1() asm volatile("cp.async.wait_group 1;" ::: "memory")
#define CP_WAIT0() asm volatile("cp.async.wait_group 0;" ::: "memory")

// m16n8k16 fp16 MMA, fp32 accumulate (sm_80+, valid at compute_103)
__device__ __forceinline__ void mma_f16(
    float& d0, float& d1, float& d2, float& d3,
    uint32_t a0, uint32_t a1, uint32_t a2, uint32_t a3,
    uint32_t b0, uint32_t b1)
{
    asm volatile(
        "mma.sync.aligned.m16n8k16.row.col.f32.f16.f16.f32 "
        "{%0,%1,%2,%3}, {%4,%5,%6,%7}, {%8,%9}, {%0,%1,%2,%3};"
        : "+f"(d0), "+f"(d1), "+f"(d2), "+f"(d3)
        : "r"(a0), "r"(a1), "r"(a2), "r"(a3), "r"(b0), "r"(b1));
}

// ---------------------------------------------------------------------------
// Fused fp16 conversion + K-pair permute over x, w_qkv, w_proj.
// Thread handles one 16-float K-block -> 8 half2 in order [0,4,1,5,2,6,3,7].
// ---------------------------------------------------------------------------
#define N16_X  (Mz * Dz / 16)
#define N16_WQ (D3z * Dz / 16)
#define N16_WP (Dz * Dz / 16)

__global__ __launch_bounds__(256) void cvt_all_kernel(
    const float* __restrict__ x,  uint32_t* __restrict__ xo,
    const float* __restrict__ wq, uint32_t* __restrict__ wqo,
    const float* __restrict__ wp, uint32_t* __restrict__ wpo)
{
    int i = blockIdx.x * blockDim.x + threadIdx.x;
    const float4* src;
    uint4* dst;
    int j;
    if (i < N16_X)                { src = (const float4*)x;  dst = (uint4*)xo;  j = i; }
    else if (i < N16_X + N16_WQ)  { src = (const float4*)wq; dst = (uint4*)wqo; j = i - N16_X; }
    else if (i < N16_X + N16_WQ + N16_WP)
                                  { src = (const float4*)wp; dst = (uint4*)wpo; j = i - N16_X - N16_WQ; }
    else return;
    float4 v0 = src[4 * j], v1 = src[4 * j + 1];
    float4 v2 = src[4 * j + 2], v3 = src[4 * j + 3];
    uint32_t m0 = f2h2(v0.x, v0.y), m1 = f2h2(v0.z, v0.w);
    uint32_t m2 = f2h2(v1.x, v1.y), m3 = f2h2(v1.z, v1.w);
    uint32_t m4 = f2h2(v2.x, v2.y), m5 = f2h2(v2.z, v2.w);
    uint32_t m6 = f2h2(v3.x, v3.y), m7 = f2h2(v3.z, v3.w);
    dst[2 * j]     = make_uint4(m0, m4, m1, m5);
    dst[2 * j + 1] = make_uint4(m2, m6, m3, m7);
}

// ---------------------------------------------------------------------------
// fp16 mma.sync NT GEMM on permuted fp16 inputs. C fp32. (unchanged from R9)
// ---------------------------------------------------------------------------
#define STAGES 3
#define BKH 32
#define AST32 24
#define STAGE_U32 (128 * AST32 * 2)            // 6144 uint32
#define GEMM_SMEM (STAGES * STAGE_U32 * 4)     // 73728 bytes

__global__ __launch_bounds__(256, 2)
void gemm_mma_kernel(const uint32_t* __restrict__ A, const uint32_t* __restrict__ B,
                     float* __restrict__ C, int M, int N, int K)
{
    extern __shared__ uint32_t smu[];
    uint32_t sb = smem_u32(smu);
    const int tid = threadIdx.x;
    const int wid = tid >> 5;
    const int l   = tid & 31;
    const int g   = l >> 2;
    const int tg  = l & 3;
    const int wm  = wid >> 1;
    const int wn  = wid & 1;
    const int m0  = blockIdx.y * 128;
    const int n0  = blockIdx.x * 128;
    const int nchunk = K / BKH;
    const int rs  = K / 2;              // uint32 per gmem row

    auto issue = [&](int c, int s) {
        uint32_t sA = sb + (uint32_t)s * STAGE_U32 * 4;
        uint32_t sB = sA + 128u * AST32 * 4;
        const uint32_t* Ab = A + (size_t)m0 * rs + c * (BKH / 2);
        const uint32_t* Bb = B + (size_t)n0 * rs + c * (BKH / 2);
        #pragma unroll
        for (int i = 0; i < 2; i++) {
            int idx = tid + 256 * i;        // 0..511
            int row = idx >> 2;
            int c4  = idx & 3;
            uint32_t so = (uint32_t)(row * AST32 + c4 * 4) * 4;
            CP_ASYNC16(sA + so, Ab + (size_t)row * rs + c4 * 4);
            CP_ASYNC16(sB + so, Bb + (size_t)row * rs + c4 * 4);
        }
        CP_COMMIT();
    };

    float acc[2][8][4];
    #pragma unroll
    for (int mt = 0; mt < 2; mt++)
        #pragma unroll
        for (int nt = 0; nt < 8; nt++)
            #pragma unroll
            for (int q = 0; q < 4; q++) acc[mt][nt][q] = 0.f;

    issue(0, 0);
    issue(1, 1);

    const int abase = (wm * 32 + g) * AST32 + 2 * tg;
    const int bbase = (wn * 64 + g) * AST32 + 2 * tg;

    for (int c = 0; c < nchunk; c++) {
        if (c == nchunk - 1) { CP_WAIT0(); } else { CP_WAIT1(); }
        __syncthreads();

        int cn = c + 2;
        if (cn < nchunk) issue(cn, cn % STAGES);

        const uint32_t* Au = smu + (size_t)(c % STAGES) * STAGE_U32;
        const uint32_t* Bu = Au + 128 * AST32;

        #pragma unroll
        for (int s = 0; s < 2; s++) {
            uint32_t a[2][4];
            #pragma unroll
            for (int mt = 0; mt < 2; mt++) {
                uint2 lo = *(const uint2*)&Au[abase + mt * 16 * AST32 + s * 8];
                uint2 hi = *(const uint2*)&Au[abase + mt * 16 * AST32 + 8 * AST32 + s * 8];
                a[mt][0] = lo.x; a[mt][2] = lo.y;
                a[mt][1] = hi.x; a[mt][3] = hi.y;
            }
            uint32_t b[8][2];
            #pragma unroll
            for (int nt = 0; nt < 8; nt++) {
                uint2 bv = *(const uint2*)&Bu[bbase + nt * 8 * AST32 + s * 8];
                b[nt][0] = bv.x; b[nt][1] = bv.y;
            }
            #pragma unroll
            for (int mt = 0; mt < 2; mt++)
                #pragma unroll
                for (int nt = 0; nt < 8; nt++)
                    mma_f16(acc[mt][nt][0], acc[mt][nt][1],
                            acc[mt][nt][2], acc[mt][nt][3],
                            a[mt][0], a[mt][1], a[mt][2], a[mt][3],
                            b[nt][0], b[nt][1]);
        }
    }

    #pragma unroll
    for (int mt = 0; mt < 2; mt++) {
        int r = m0 + wm * 32 + mt * 16 + g;
        #pragma unroll
        for (int nt = 0; nt < 8; nt++) {
            int cc = n0 + wn * 64 + nt * 8 + tg * 2;
            *(float2*)&C[(size_t)r * N + cc] =
                make_float2(acc[mt][nt][0], acc[mt][nt][1]);
            *(float2*)&C[(size_t)(r + 8) * N + cc] =
                make_float2(acc[mt][nt][2], acc[mt][nt][3]);
        }
    }
}

// ---------------------------------------------------------------------------
// Flash attention: QK^T AND PV in fp16 (m16n8k16), fp32 accumulate.
// P A-fragments come straight from the S-accumulator registers (layouts
// match) — no P SMEM round-trip. V is transposed at load via shfl.xor(16)
// into half2-over-key-pairs (Vt). QTILE=64, 4 CTAs/SM, longest CTAs first.
// ---------------------------------------------------------------------------
#define KST32 36     // K tile: 64 key-rows x 32 u32 (half2 over d), stride 36
#define VTS   36     // Vt: 64 d-rows x 32 u32 (half2 over key pairs), stride 36
#define QST   36     // Q staging (aliases Vt region)
#define ATT_U32 (64 * KST32 + 64 * VTS)
#define ATT_SMEM (ATT_U32 * 4)     // 18432 bytes

__global__ __launch_bounds__(128, 4) void attn_mma_kernel(
    const float* __restrict__ qkv, uint32_t* __restrict__ out)
{
    extern __shared__ uint32_t smu[];
    uint32_t* Kh = smu;
    uint32_t* Vt = smu + 64 * KST32;
    uint32_t* Qs = Vt;                 // alias: Q staged before any V write

    const int tid = threadIdx.x;
    const int w  = tid >> 5;
    const int l  = tid & 31;
    const int g  = l >> 2;
    const int tg = l & 3;
    const int qt = gridDim.x - 1 - blockIdx.x;   // longest work first
    const int h  = blockIdx.y;
    const int b  = blockIdx.z;
    const int q0 = qt * 64;
    const size_t bh = (size_t)b * Sz * D3z + (size_t)h * HDz;
    const float NEG_INF = -__int_as_float(0x7f800000);

    // Stage Q (scaled by 1/8) as half2-over-d into Qs
    for (int idx = tid; idx < 1024; idx += 128) {
        int r = idx >> 4, c4 = idx & 15;
        float4 v = *(const float4*)(qkv + bh + (size_t)(q0 + r) * D3z + c4 * 4);
        Qs[r * QST + 2 * c4]     = f2h2(v.x * 0.125f, v.y * 0.125f);
        Qs[r * QST + 2 * c4 + 1] = f2h2(v.z * 0.125f, v.w * 0.125f);
    }
    __syncthreads();

    // Q A-fragments for 4 k16-steps over d
    uint32_t qa[4][4];
    const int qr0 = (w * 16 + g) * QST;
    const int qr1 = qr0 + 8 * QST;
    #pragma unroll
    for (int s = 0; s < 4; s++) {
        qa[s][0] = Qs[qr0 + s * 8 + tg];
        qa[s][1] = Qs[qr1 + s * 8 + tg];
        qa[s][2] = Qs[qr0 + s * 8 + tg + 4];
        qa[s][3] = Qs[qr1 + s * 8 + tg + 4];
    }

    float o[8][4];
    #pragma unroll
    for (int nt = 0; nt < 8; nt++)
        #pragma unroll
        for (int q = 0; q < 4; q++) o[nt][q] = 0.f;
    float m0 = NEG_INF, m1 = NEG_INF, l0 = 0.f, l1 = 0.f;

    for (int kt = 0; kt <= qt; kt++) {
        const int k0 = kt * 64;
        __syncthreads();   // prior tile's readers done (also covers Qs alias)
        for (int idx = tid; idx < 1024; idx += 128) {
            int r = idx >> 4, c4 = idx & 15;
            const float* p = qkv + bh + (size_t)(k0 + r) * D3z + Dz + c4 * 4;
            float4 kv = *(const float4*)p;
            float4 vv = *(const float4*)(p + Dz);
            // K: half2 over d, row = key
            Kh[r * KST32 + 2 * c4]     = f2h2(kv.x, kv.y);
            Kh[r * KST32 + 2 * c4 + 1] = f2h2(kv.z, kv.w);
            // V: transpose via lane^16 exchange (rows r even / r+1 odd in warp)
            float4 ov;
            ov.x = __shfl_xor_sync(0xffffffffu, vv.x, 16);
            ov.y = __shfl_xor_sync(0xffffffffu, vv.y, 16);
            ov.z = __shfl_xor_sync(0xffffffffu, vv.z, 16);
            ov.w = __shfl_xor_sync(0xffffffffu, vv.w, 16);
            int jp = r >> 1;
            int d0 = c4 * 4;
            if ((l & 16) == 0) {   // own = even key row, partner = odd
                Vt[(d0 + 0) * VTS + jp] = f2h2(vv.x, ov.x);
                Vt[(d0 + 1) * VTS + jp] = f2h2(vv.y, ov.y);
            } else {               // own = odd key row, partner = even
                Vt[(d0 + 2) * VTS + jp] = f2h2(ov.z, vv.z);
                Vt[(d0 + 3) * VTS + jp] = f2h2(ov.w, vv.w);
            }
        }
        __syncthreads();

        // Scores S = Q K^T (fp16, 4 k-steps over d)
        float s[8][4];
        #pragma unroll
        for (int nt = 0; nt < 8; nt++)
            #pragma unroll
            for (int q = 0; q < 4; q++) s[nt][q] = 0.f;

        #pragma unroll
        for (int ks = 0; ks < 4; ks++) {
            #pragma unroll
            for (int nt = 0; nt < 8; nt++) {
                int kb = (nt * 8 + g) * KST32 + ks * 8 + tg;
                uint32_t b0 = Kh[kb];
                uint32_t b1 = Kh[kb + 4];
                mma_f16(s[nt][0], s[nt][1], s[nt][2], s[nt][3],
                        qa[ks][0], qa[ks][1], qa[ks][2], qa[ks][3], b0, b1);
            }
        }

        if (kt == qt) {
            int i0 = w * 16 + g, i1 = i0 + 8;
            #pragma unroll
            for (int nt = 0; nt < 8; nt++) {
                int j0 = nt * 8 + 2 * tg;
                if (j0     > i0) s[nt][0] = NEG_INF;
                if (j0 + 1 > i0) s[nt][1] = NEG_INF;
                if (j0     > i1) s[nt][2] = NEG_INF;
                if (j0 + 1 > i1) s[nt][3] = NEG_INF;
            }
        }

        // Online softmax (rows g, g+8; quad-lane reductions)
        float r0 = NEG_INF, r1 = NEG_INF;
        #pragma unroll
        for (int nt = 0; nt < 8; nt++) {
            r0 = fmaxf(r0, fmaxf(s[nt][0], s[nt][1]));
            r1 = fmaxf(r1, fmaxf(s[nt][2], s[nt][3]));
        }
        r0 = fmaxf(r0, __shfl_xor_sync(0xffffffffu, r0, 1));
        r0 = fmaxf(r0, __shfl_xor_sync(0xffffffffu, r0, 2));
        r1 = fmaxf(r1, __shfl_xor_sync(0xffffffffu, r1, 1));
        r1 = fmaxf(r1, __shfl_xor_sync(0xffffffffu, r1, 2));

        float nm0 = fmaxf(m0, r0), nm1 = fmaxf(m1, r1);
        float a0 = __expf(m0 - nm0), a1 = __expf(m1 - nm1);
        float sum0 = 0.f, sum1 = 0.f;
        #pragma unroll
        for (int nt = 0; nt < 8; nt++) {
            s[nt][0] = __expf(s[nt][0] - nm0);
            s[nt][1] = __expf(s[nt][1] - nm0);
            s[nt][2] = __expf(s[nt][2] - nm1);
            s[nt][3] = __expf(s[nt][3] - nm1);
            sum0 += s[nt][0] + s[nt][1];
            sum1 += s[nt][2] + s[nt][3];
        }
        sum0 += __shfl_xor_sync(0xffffffffu, sum0, 1);
        sum0 += __shfl_xor_sync(0xffffffffu, sum0, 2);
        sum1 += __shfl_xor_sync(0xffffffffu, sum1, 1);
        sum1 += __shfl_xor_sync(0xffffffffu, sum1, 2);
        m0 = nm0; m1 = nm1;
        l0 = l0 * a0 + sum0;
        l1 = l1 * a1 + sum1;

        #pragma unroll
        for (int nt = 0; nt < 8; nt++) {
            o[nt][0] *= a0; o[nt][1] *= a0;
            o[nt][2] *= a1; o[nt][3] *= a1;
        }

        // O += P V: fp16 MMA; P A-frags packed straight from s registers.
        #pragma unroll
        for (int ks = 0; ks < 4; ks++) {
            uint32_t pa0 = f2h2(s[2 * ks][0],     s[2 * ks][1]);
            uint32_t pa1 = f2h2(s[2 * ks][2],     s[2 * ks][3]);
            uint32_t pa2 = f2h2(s[2 * ks + 1][0], s[2 * ks + 1][1]);
            uint32_t pa3 = f2h2(s[2 * ks + 1][2], s[2 * ks + 1][3]);
            #pragma unroll
            for (int nt = 0; nt < 8; nt++) {
                int vb = (nt * 8 + g) * VTS + ks * 8 + tg;
                uint32_t b0 = Vt[vb];
                uint32_t b1 = Vt[vb + 4];
                mma_f16(o[nt][0], o[nt][1], o[nt][2], o[nt][3],
                        pa0, pa1, pa2, pa3, b0, b1);
            }
        }
    }

    // Epilogue: scale by 1/l, write K-pair-PERMUTED fp16 for the proj GEMM.
    float i0v = 1.f / l0, i1v = 1.f / l1;
    uint32_t* o0p = out + ((size_t)(b * Sz + q0 + w * 16 + g) * Dz + h * HDz) / 2;
    uint32_t* o1p = o0p + (size_t)8 * Dz / 2;
    #pragma unroll
    for (int nt = 0; nt < 8; nt++) {
        int slot = (nt & 1) ? (2 * tg + 1) : (2 * tg);
        int oidx = (nt >> 1) * 8 + slot;
        o0p[oidx] = f2h2(o[nt][0] * i0v, o[nt][1] * i0v);
        o1p[oidx] = f2h2(o[nt][2] * i1v, o[nt][3] * i1v);
    }
}

// ---------------------------------------------------------------------------
extern "C" void kernel_launch(void* const* d_in, const int* in_sizes, int n_in,
                              void* d_out, int out_size)
{
    const float* x      = (const float*)d_in[0];
    const float* w_qkv  = (const float*)d_in[1];
    const float* w_proj = (const float*)d_in[2];
    float* out = (float*)d_out;

    void *qkvp, *attnp, *xp, *wqp, *wpp;
    cudaGetSymbolAddress(&qkvp, g_qkv);
    cudaGetSymbolAddress(&attnp, g_attn);
    cudaGetSymbolAddress(&xp, g_x);
    cudaGetSymbolAddress(&wqp, g_wq);
    cudaGetSymbolAddress(&wpp, g_wp);

    cudaFuncSetAttribute(attn_mma_kernel,
                         cudaFuncAttributeMaxDynamicSharedMemorySize, ATT_SMEM);
    cudaFuncSetAttribute(gemm_mma_kernel,
                         cudaFuncAttributeMaxDynamicSharedMemorySize, GEMM_SMEM);

    const int M = Mz;

    // 0) fp16-convert + K-pair-permute all GEMM inputs
    {
        int total = N16_X + N16_WQ + N16_WP;
        cvt_all_kernel<<<(total + 255) / 256, 256>>>(
            x, (uint32_t*)xp, w_qkv, (uint32_t*)wqp, w_proj, (uint32_t*)wpp);
    }

    // 1) QKV projection (fp16 tensor cores): [8192,1024] x [3072,1024]^T
    gemm_mma_kernel<<<dim3(D3z / 128, M / 128), 256, GEMM_SMEM>>>(
        (const uint32_t*)xp, (const uint32_t*)wqp, (float*)qkvp, M, D3z, Dz);

    // 2) Causal flash attention (all-fp16 MMAs) -> g_attn (fp16, permuted)
    attn_mma_kernel<<<dim3(Sz / 64, Hz, Bz), 128, ATT_SMEM>>>(
        (const float*)qkvp, (uint32_t*)attnp);

    // 3) Output projection (fp16 tensor cores): [8192,1024] x [1024,1024]^T
    gemm_mma_kernel<<<dim3(Dz / 128, M / 128), 256, GEMM_SMEM>>>(
        (const uint32_t*)attnp, (const uint32_t*)wpp, out, M, Dz, Dz);
}

// round 11
// speedup vs baseline: 1.4110x; 1.4110x over previous
#include <cuda_runtime.h>
#include <cuda_fp16.h>
#include <cstdint>
#include <math.h>

// Problem constants
#define Bz 4
#define Sz 2048
#define Dz 1024
#define Hz 16
#define HDz 64
#define D3z 3072
#define Mz (Bz * Sz)

// Scratch (device globals: allocation-free per harness rules)
// fp16 buffers are K-pair-permuted: within each 16-element K-block, half2
// pairs are ordered [m0,m4,m1,m5,m2,m6,m3,m7] (m = pair (2m,2m+1)).
__device__ float    g_qkv[(size_t)Mz * D3z];      // [8192,3072] fp32
__device__ uint32_t g_attn[(size_t)Mz * Dz / 2];  // fp16, permuted
__device__ uint32_t g_x  [(size_t)Mz * Dz / 2];   // fp16, permuted
__device__ uint32_t g_wq [(size_t)D3z * Dz / 2];  // fp16, permuted
__device__ uint32_t g_wp [(size_t)Dz * Dz / 2];   // fp16, permuted

// ---------------------------------------------------------------------------
// Helpers
// ---------------------------------------------------------------------------
__device__ __forceinline__ uint32_t smem_u32(const void* p) {
    uint32_t a;
    asm("{ .reg .u64 t; cvta.to.shared.u64 t, %1; cvt.u32.u64 %0, t; }"
        : "=r"(a) : "l"(p));
    return a;
}

__device__ __forceinline__ uint32_t f2h2(float a, float b) {
    __half2 h = __floats2half2_rn(a, b);   // low 16 bits = a
    return *(uint32_t*)&h;
}

#define CP_ASYNC16(dst, src) \
    asm volatile("cp.async.cg.shared.global [%0], [%1], 16;" \
        :: "r"((uint32_t)(dst)), "l"(src) : "memory")
#define CP_COMMIT() asm volatile("cp.async.commit_group;" ::: "memory")
#define CP_WAIT1() asm volatile("cp.async.wait_group 1;" ::: "memory")
#define CP_WAIT0() asm volatile("cp.async.wait_group 0;" ::: "memory")

// m16n8k16 fp16 MMA, fp32 accumulate (sm_80+, valid at compute_103)
__device__ __forceinline__ void mma_f16(
    float& d0, float& d1, float& d2, float& d3,
    uint32_t a0, uint32_t a1, uint32_t a2, uint32_t a3,
    uint32_t b0, uint32_t b1)
{
    asm volatile(
        "mma.sync.aligned.m16n8k16.row.col.f32.f16.f16.f32 "
        "{%0,%1,%2,%3}, {%4,%5,%6,%7}, {%8,%9}, {%0,%1,%2,%3};"
        : "+f"(d0), "+f"(d1), "+f"(d2), "+f"(d3)
        : "r"(a0), "r"(a1), "r"(a2), "r"(a3), "r"(b0), "r"(b1));
}

// ldmatrix x4 transposed (sm_75+, valid at compute_103)
#define LDMATRIX_X4_TRANS(r0, r1, r2, r3, addr) \
    asm volatile("ldmatrix.sync.aligned.m8n8.x4.trans.shared.b16 " \
        "{%0,%1,%2,%3}, [%4];" \
        : "=r"(r0), "=r"(r1), "=r"(r2), "=r"(r3) : "r"(addr))

// ---------------------------------------------------------------------------
// Fused fp16 conversion + K-pair permute over x, w_qkv, w_proj.
// Thread handles one 16-float K-block -> 8 half2 in order [0,4,1,5,2,6,3,7].
// ---------------------------------------------------------------------------
#define N16_X  (Mz * Dz / 16)
#define N16_WQ (D3z * Dz / 16)
#define N16_WP (Dz * Dz / 16)

__global__ __launch_bounds__(256) void cvt_all_kernel(
    const float* __restrict__ x,  uint32_t* __restrict__ xo,
    const float* __restrict__ wq, uint32_t* __restrict__ wqo,
    const float* __restrict__ wp, uint32_t* __restrict__ wpo)
{
    int i = blockIdx.x * blockDim.x + threadIdx.x;
    const float4* src;
    uint4* dst;
    int j;
    if (i < N16_X)                { src = (const float4*)x;  dst = (uint4*)xo;  j = i; }
    else if (i < N16_X + N16_WQ)  { src = (const float4*)wq; dst = (uint4*)wqo; j = i - N16_X; }
    else if (i < N16_X + N16_WQ + N16_WP)
                                  { src = (const float4*)wp; dst = (uint4*)wpo; j = i - N16_X - N16_WQ; }
    else return;
    float4 v0 = src[4 * j], v1 = src[4 * j + 1];
    float4 v2 = src[4 * j + 2], v3 = src[4 * j + 3];
    uint32_t m0 = f2h2(v0.x, v0.y), m1 = f2h2(v0.z, v0.w);
    uint32_t m2 = f2h2(v1.x, v1.y), m3 = f2h2(v1.z, v1.w);
    uint32_t m4 = f2h2(v2.x, v2.y), m5 = f2h2(v2.z, v2.w);
    uint32_t m6 = f2h2(v3.x, v3.y), m7 = f2h2(v3.z, v3.w);
    dst[2 * j]     = make_uint4(m0, m4, m1, m5);
    dst[2 * j + 1] = make_uint4(m2, m6, m3, m7);
}

// ---------------------------------------------------------------------------
// fp16 mma.sync NT GEMM on permuted fp16 inputs. C fp32. (unchanged from R9)
// ---------------------------------------------------------------------------
#define STAGES 3
#define BKH 32
#define AST32 24
#define STAGE_U32 (128 * AST32 * 2)            // 6144 uint32
#define GEMM_SMEM (STAGES * STAGE_U32 * 4)     // 73728 bytes

__global__ __launch_bounds__(256, 2)
void gemm_mma_kernel(const uint32_t* __restrict__ A, const uint32_t* __restrict__ B,
                     float* __restrict__ C, int M, int N, int K)
{
    extern __shared__ uint32_t smu[];
    uint32_t sb = smem_u32(smu);
    const int tid = threadIdx.x;
    const int wid = tid >> 5;
    const int l   = tid & 31;
    const int g   = l >> 2;
    const int tg  = l & 3;
    const int wm  = wid >> 1;
    const int wn  = wid & 1;
    const int m0  = blockIdx.y * 128;
    const int n0  = blockIdx.x * 128;
    const int nchunk = K / BKH;
    const int rs  = K / 2;              // uint32 per gmem row

    auto issue = [&](int c, int s) {
        uint32_t sA = sb + (uint32_t)s * STAGE_U32 * 4;
        uint32_t sB = sA + 128u * AST32 * 4;
        const uint32_t* Ab = A + (size_t)m0 * rs + c * (BKH / 2);
        const uint32_t* Bb = B + (size_t)n0 * rs + c * (BKH / 2);
        #pragma unroll
        for (int i = 0; i < 2; i++) {
            int idx = tid + 256 * i;        // 0..511
            int row = idx >> 2;
            int c4  = idx & 3;
            uint32_t so = (uint32_t)(row * AST32 + c4 * 4) * 4;
            CP_ASYNC16(sA + so, Ab + (size_t)row * rs + c4 * 4);
            CP_ASYNC16(sB + so, Bb + (size_t)row * rs + c4 * 4);
        }
        CP_COMMIT();
    };

    float acc[2][8][4];
    #pragma unroll
    for (int mt = 0; mt < 2; mt++)
        #pragma unroll
        for (int nt = 0; nt < 8; nt++)
            #pragma unroll
            for (int q = 0; q < 4; q++) acc[mt][nt][q] = 0.f;

    issue(0, 0);
    issue(1, 1);

    const int abase = (wm * 32 + g) * AST32 + 2 * tg;
    const int bbase = (wn * 64 + g) * AST32 + 2 * tg;

    for (int c = 0; c < nchunk; c++) {
        if (c == nchunk - 1) { CP_WAIT0(); } else { CP_WAIT1(); }
        __syncthreads();

        int cn = c + 2;
        if (cn < nchunk) issue(cn, cn % STAGES);

        const uint32_t* Au = smu + (size_t)(c % STAGES) * STAGE_U32;
        const uint32_t* Bu = Au + 128 * AST32;

        #pragma unroll
        for (int s = 0; s < 2; s++) {
            uint32_t a[2][4];
            #pragma unroll
            for (int mt = 0; mt < 2; mt++) {
                uint2 lo = *(const uint2*)&Au[abase + mt * 16 * AST32 + s * 8];
                uint2 hi = *(const uint2*)&Au[abase + mt * 16 * AST32 + 8 * AST32 + s * 8];
                a[mt][0] = lo.x; a[mt][2] = lo.y;
                a[mt][1] = hi.x; a[mt][3] = hi.y;
            }
            uint32_t b[8][2];
            #pragma unroll
            for (int nt = 0; nt < 8; nt++) {
                uint2 bv = *(const uint2*)&Bu[bbase + nt * 8 * AST32 + s * 8];
                b[nt][0] = bv.x; b[nt][1] = bv.y;
            }
            #pragma unroll
            for (int mt = 0; mt < 2; mt++)
                #pragma unroll
                for (int nt = 0; nt < 8; nt++)
                    mma_f16(acc[mt][nt][0], acc[mt][nt][1],
                            acc[mt][nt][2], acc[mt][nt][3],
                            a[mt][0], a[mt][1], a[mt][2], a[mt][3],
                            b[nt][0], b[nt][1]);
        }
    }

    #pragma unroll
    for (int mt = 0; mt < 2; mt++) {
        int r = m0 + wm * 32 + mt * 16 + g;
        #pragma unroll
        for (int nt = 0; nt < 8; nt++) {
            int cc = n0 + wn * 64 + nt * 8 + tg * 2;
            *(float2*)&C[(size_t)r * N + cc] =
                make_float2(acc[mt][nt][0], acc[mt][nt][1]);
            *(float2*)&C[(size_t)(r + 8) * N + cc] =
                make_float2(acc[mt][nt][2], acc[mt][nt][3]);
        }
    }
}

// ---------------------------------------------------------------------------
// Flash attention, all-fp16 MMAs. QK^T: B-frags from Kh via LDS.64.
// PV: P A-frags straight from S-accumulator registers; V B-frags via
// ldmatrix.x4.trans on V stored in natural [key][d] fp16 layout (no shuffle
// transpose, conflict-free stores). QTILE=64, 4 CTAs/SM, longest CTAs first.
// ---------------------------------------------------------------------------
#define KST32 36     // K tile: 64 key-rows x 32 u32 (half2 over d), stride 36
#define VST32 36     // V tile: same layout as K
#define QST   36     // Q staging (aliases V region)
#define ATT_U32 (64 * KST32 + 64 * VST32)
#define ATT_SMEM (ATT_U32 * 4)     // 18432 bytes

__global__ __launch_bounds__(128, 4) void attn_mma_kernel(
    const float* __restrict__ qkv, uint32_t* __restrict__ out)
{
    extern __shared__ uint32_t smu[];
    uint32_t* Kh = smu;
    uint32_t* Vh = smu + 64 * KST32;
    uint32_t* Qs = Vh;                 // alias: Q staged before any V write
    const uint32_t sb = smem_u32(smu);
    const uint32_t vbase = sb + 64u * KST32 * 4u;

    const int tid = threadIdx.x;
    const int w  = tid >> 5;
    const int l  = tid & 31;
    const int g  = l >> 2;
    const int tg = l & 3;
    const int qt = gridDim.x - 1 - blockIdx.x;   // longest work first
    const int h  = blockIdx.y;
    const int b  = blockIdx.z;
    const int q0 = qt * 64;
    const size_t bh = (size_t)b * Sz * D3z + (size_t)h * HDz;
    const float NEG_INF = -__int_as_float(0x7f800000);

    // ldmatrix lane address base: mat = l>>3; row = (mat&1)*8 + (l&7);
    // col_u32 = (mat>>1)*4. Full addr adds (ks*16*VST32 + ntp*8)*4.
    const uint32_t vlane = vbase +
        ((((l >> 3) & 1) * 8 + (l & 7)) * VST32 + (l >> 4) * 4) * 4u;

    // Stage Q (scaled by 1/8) as half2-over-d into Qs
    for (int idx = tid; idx < 1024; idx += 128) {
        int r = idx >> 4, c4 = idx & 15;
        float4 v = *(const float4*)(qkv + bh + (size_t)(q0 + r) * D3z + c4 * 4);
        Qs[r * QST + 2 * c4]     = f2h2(v.x * 0.125f, v.y * 0.125f);
        Qs[r * QST + 2 * c4 + 1] = f2h2(v.z * 0.125f, v.w * 0.125f);
    }
    __syncthreads();

    // Q A-fragments for 4 k16-steps over d
    uint32_t qa[4][4];
    const int qr0 = (w * 16 + g) * QST;
    const int qr1 = qr0 + 8 * QST;
    #pragma unroll
    for (int s = 0; s < 4; s++) {
        qa[s][0] = Qs[qr0 + s * 8 + tg];
        qa[s][1] = Qs[qr1 + s * 8 + tg];
        qa[s][2] = Qs[qr0 + s * 8 + tg + 4];
        qa[s][3] = Qs[qr1 + s * 8 + tg + 4];
    }

    float o[8][4];
    #pragma unroll
    for (int nt = 0; nt < 8; nt++)
        #pragma unroll
        for (int q = 0; q < 4; q++) o[nt][q] = 0.f;
    float m0 = NEG_INF, m1 = NEG_INF, l0 = 0.f, l1 = 0.f;

    for (int kt = 0; kt <= qt; kt++) {
        const int k0 = kt * 64;
        __syncthreads();   // prior tile's readers done (also covers Qs alias)
        for (int idx = tid; idx < 1024; idx += 128) {
            int r = idx >> 4, c4 = idx & 15;
            const float* p = qkv + bh + (size_t)(k0 + r) * D3z + Dz + c4 * 4;
            float4 kv = *(const float4*)p;
            float4 vv = *(const float4*)(p + Dz);
            Kh[r * KST32 + 2 * c4]     = f2h2(kv.x, kv.y);
            Kh[r * KST32 + 2 * c4 + 1] = f2h2(kv.z, kv.w);
            Vh[r * VST32 + 2 * c4]     = f2h2(vv.x, vv.y);
            Vh[r * VST32 + 2 * c4 + 1] = f2h2(vv.z, vv.w);
        }
        __syncthreads();

        // Scores S = Q K^T (fp16, 4 k-steps over d)
        float s[8][4];
        #pragma unroll
        for (int nt = 0; nt < 8; nt++)
            #pragma unroll
            for (int q = 0; q < 4; q++) s[nt][q] = 0.f;

        #pragma unroll
        for (int ks = 0; ks < 4; ks++) {
            #pragma unroll
            for (int nt = 0; nt < 8; nt++) {
                int kb = (nt * 8 + g) * KST32 + ks * 8 + tg;
                uint32_t b0 = Kh[kb];
                uint32_t b1 = Kh[kb + 4];
                mma_f16(s[nt][0], s[nt][1], s[nt][2], s[nt][3],
                        qa[ks][0], qa[ks][1], qa[ks][2], qa[ks][3], b0, b1);
            }
        }

        if (kt == qt) {
            int i0 = w * 16 + g, i1 = i0 + 8;
            #pragma unroll
            for (int nt = 0; nt < 8; nt++) {
                int j0 = nt * 8 + 2 * tg;
                if (j0     > i0) s[nt][0] = NEG_INF;
                if (j0 + 1 > i0) s[nt][1] = NEG_INF;
                if (j0     > i1) s[nt][2] = NEG_INF;
                if (j0 + 1 > i1) s[nt][3] = NEG_INF;
            }
        }

        // Online softmax (rows g, g+8; quad-lane reductions)
        float r0 = NEG_INF, r1 = NEG_INF;
        #pragma unroll
        for (int nt = 0; nt < 8; nt++) {
            r0 = fmaxf(r0, fmaxf(s[nt][0], s[nt][1]));
            r1 = fmaxf(r1, fmaxf(s[nt][2], s[nt][3]));
        }
        r0 = fmaxf(r0, __shfl_xor_sync(0xffffffffu, r0, 1));
        r0 = fmaxf(r0, __shfl_xor_sync(0xffffffffu, r0, 2));
        r1 = fmaxf(r1, __shfl_xor_sync(0xffffffffu, r1, 1));
        r1 = fmaxf(r1, __shfl_xor_sync(0xffffffffu, r1, 2));

        float nm0 = fmaxf(m0, r0), nm1 = fmaxf(m1, r1);
        float a0 = __expf(m0 - nm0), a1 = __expf(m1 - nm1);
        float sum0 = 0.f, sum1 = 0.f;
        #pragma unroll
        for (int nt = 0; nt < 8; nt++) {
            s[nt][0] = __expf(s[nt][0] - nm0);
            s[nt][1] = __expf(s[nt][1] - nm0);
            s[nt][2] = __expf(s[nt][2] - nm1);
            s[nt][3] = __expf(s[nt][3] - nm1);
            sum0 += s[nt][0] + s[nt][1];
            sum1 += s[nt][2] + s[nt][3];
        }
        sum0 += __shfl_xor_sync(0xffffffffu, sum0, 1);
        sum0 += __shfl_xor_sync(0xffffffffu, sum0, 2);
        sum1 += __shfl_xor_sync(0xffffffffu, sum1, 1);
        sum1 += __shfl_xor_sync(0xffffffffu, sum1, 2);
        m0 = nm0; m1 = nm1;
        l0 = l0 * a0 + sum0;
        l1 = l1 * a1 + sum1;

        #pragma unroll
        for (int nt = 0; nt < 8; nt++) {
            o[nt][0] *= a0; o[nt][1] *= a0;
            o[nt][2] *= a1; o[nt][3] *= a1;
        }

        // O += P V: P A-frags from s registers; V B-frags via ldmatrix.trans
        #pragma unroll
        for (int ks = 0; ks < 4; ks++) {
            uint32_t pa0 = f2h2(s[2 * ks][0],     s[2 * ks][1]);
            uint32_t pa1 = f2h2(s[2 * ks][2],     s[2 * ks][3]);
            uint32_t pa2 = f2h2(s[2 * ks + 1][0], s[2 * ks + 1][1]);
            uint32_t pa3 = f2h2(s[2 * ks + 1][2], s[2 * ks + 1][3]);
            #pragma unroll
            for (int ntp = 0; ntp < 4; ntp++) {
                uint32_t b0, b1, b2, b3;
                uint32_t addr = vlane + (uint32_t)(ks * 16 * VST32 + ntp * 8) * 4u;
                LDMATRIX_X4_TRANS(b0, b1, b2, b3, addr);
                mma_f16(o[2 * ntp][0],     o[2 * ntp][1],
                        o[2 * ntp][2],     o[2 * ntp][3],
                        pa0, pa1, pa2, pa3, b0, b1);
                mma_f16(o[2 * ntp + 1][0], o[2 * ntp + 1][1],
                        o[2 * ntp + 1][2], o[2 * ntp + 1][3],
                        pa0, pa1, pa2, pa3, b2, b3);
            }
        }
    }

    // Epilogue: scale by 1/l, write K-pair-PERMUTED fp16 for the proj GEMM.
    float i0v = 1.f / l0, i1v = 1.f / l1;
    uint32_t* o0p = out + ((size_t)(b * Sz + q0 + w * 16 + g) * Dz + h * HDz) / 2;
    uint32_t* o1p = o0p + (size_t)8 * Dz / 2;
    #pragma unroll
    for (int nt = 0; nt < 8; nt++) {
        int slot = (nt & 1) ? (2 * tg + 1) : (2 * tg);
        int oidx = (nt >> 1) * 8 + slot;
        o0p[oidx] = f2h2(o[nt][0] * i0v, o[nt][1] * i0v);
        o1p[oidx] = f2h2(o[nt][2] * i1v, o[nt][3] * i1v);
    }
}

// ---------------------------------------------------------------------------
extern "C" void kernel_launch(void* const* d_in, const int* in_sizes, int n_in,
                              void* d_out, int out_size)
{
    const float* x      = (const float*)d_in[0];
    const float* w_qkv  = (const float*)d_in[1];
    const float* w_proj = (const float*)d_in[2];
    float* out = (float*)d_out;

    void *qkvp, *attnp, *xp, *wqp, *wpp;
    cudaGetSymbolAddress(&qkvp, g_qkv);
    cudaGetSymbolAddress(&attnp, g_attn);
    cudaGetSymbolAddress(&xp, g_x);
    cudaGetSymbolAddress(&wqp, g_wq);
    cudaGetSymbolAddress(&wpp, g_wp);

    cudaFuncSetAttribute(attn_mma_kernel,
                         cudaFuncAttributeMaxDynamicSharedMemorySize, ATT_SMEM);
    cudaFuncSetAttribute(gemm_mma_kernel,
                         cudaFuncAttributeMaxDynamicSharedMemorySize, GEMM_SMEM);

    const int M = Mz;

    // 0) fp16-convert + K-pair-permute all GEMM inputs
    {
        int total = N16_X + N16_WQ + N16_WP;
        cvt_all_kernel<<<(total + 255) / 256, 256>>>(
            x, (uint32_t*)xp, w_qkv, (uint32_t*)wqp, w_proj, (uint32_t*)wpp);
    }

    // 1) QKV projection (fp16 tensor cores): [8192,1024] x [3072,1024]^T
    gemm_mma_kernel<<<dim3(D3z / 128, M / 128), 256, GEMM_SMEM>>>(
        (const uint32_t*)xp, (const uint32_t*)wqp, (float*)qkvp, M, D3z, Dz);

    // 2) Causal flash attention (all-fp16 MMAs, ldmatrix.trans V)
    attn_mma_kernel<<<dim3(Sz / 64, Hz, Bz), 128, ATT_SMEM>>>(
        (const float*)qkvp, (uint32_t*)attnp);

    // 3) Output projection (fp16 tensor cores): [8192,1024] x [1024,1024]^T
    gemm_mma_kernel<<<dim3(Dz / 128, M / 128), 256, GEMM_SMEM>>>(
        (const uint32_t*)attnp, (const uint32_t*)wpp, out, M, Dz, Dz);
}

// round 12
// speedup vs baseline: 1.4859x; 1.0531x over previous
#include <cuda_runtime.h>
#include <cuda_fp16.h>
#include <cstdint>
#include <math.h>

// Problem constants
#define Bz 4
#define Sz 2048
#define Dz 1024
#define Hz 16
#define HDz 64
#define D3z 3072
#define Mz (Bz * Sz)

// Scratch (device globals: allocation-free per harness rules)
// g_qkv: fp16, NATURAL half2-over-d order, Q pre-scaled by 0.125.
// g_x/g_wq/g_wp/g_attn: fp16, K-pair-permuted ([m0,m4,m1,m5,m2,m6,m3,m7]).
__device__ uint32_t g_qkv[(size_t)Mz * D3z / 2];
__device__ uint32_t g_attn[(size_t)Mz * Dz / 2];
__device__ uint32_t g_x  [(size_t)Mz * Dz / 2];
__device__ uint32_t g_wq [(size_t)D3z * Dz / 2];
__device__ uint32_t g_wp [(size_t)Dz * Dz / 2];

// ---------------------------------------------------------------------------
// Helpers
// ---------------------------------------------------------------------------
__device__ __forceinline__ uint32_t smem_u32(const void* p) {
    uint32_t a;
    asm("{ .reg .u64 t; cvta.to.shared.u64 t, %1; cvt.u32.u64 %0, t; }"
        : "=r"(a) : "l"(p));
    return a;
}

__device__ __forceinline__ uint32_t f2h2(float a, float b) {
    __half2 h = __floats2half2_rn(a, b);   // low 16 bits = a
    return *(uint32_t*)&h;
}

#define CP_ASYNC16(dst, src) \
    asm volatile("cp.async.cg.shared.global [%0], [%1], 16;" \
        :: "r"((uint32_t)(dst)), "l"(src) : "memory")
#define CP_COMMIT() asm volatile("cp.async.commit_group;" ::: "memory")
#define CP_WAIT1() asm volatile("cp.async.wait_group 1;" ::: "memory")
#define CP_WAIT0() asm volatile("cp.async.wait_group 0;" ::: "memory")

// m16n8k16 fp16 MMA, fp32 accumulate (sm_80+, valid at compute_103)
__device__ __forceinline__ void mma_f16(
    float& d0, float& d1, float& d2, float& d3,
    uint32_t a0, uint32_t a1, uint32_t a2, uint32_t a3,
    uint32_t b0, uint32_t b1)
{
    asm volatile(
        "mma.sync.aligned.m16n8k16.row.col.f32.f16.f16.f32 "
        "{%0,%1,%2,%3}, {%4,%5,%6,%7}, {%8,%9}, {%0,%1,%2,%3};"
        : "+f"(d0), "+f"(d1), "+f"(d2), "+f"(d3)
        : "r"(a0), "r"(a1), "r"(a2), "r"(a3), "r"(b0), "r"(b1));
}

// ldmatrix x4 transposed (sm_75+, valid at compute_103)
#define LDMATRIX_X4_TRANS(r0, r1, r2, r3, addr) \
    asm volatile("ldmatrix.sync.aligned.m8n8.x4.trans.shared.b16 " \
        "{%0,%1,%2,%3}, [%4];" \
        : "=r"(r0), "=r"(r1), "=r"(r2), "=r"(r3) : "r"(addr))

// ---------------------------------------------------------------------------
// Fused fp16 conversion + K-pair permute over x, w_qkv, w_proj.
// ---------------------------------------------------------------------------
#define N16_X  (Mz * Dz / 16)
#define N16_WQ (D3z * Dz / 16)
#define N16_WP (Dz * Dz / 16)

__global__ __launch_bounds__(256) void cvt_all_kernel(
    const float* __restrict__ x,  uint32_t* __restrict__ xo,
    const float* __restrict__ wq, uint32_t* __restrict__ wqo,
    const float* __restrict__ wp, uint32_t* __restrict__ wpo)
{
    int i = blockIdx.x * blockDim.x + threadIdx.x;
    const float4* src;
    uint4* dst;
    int j;
    if (i < N16_X)                { src = (const float4*)x;  dst = (uint4*)xo;  j = i; }
    else if (i < N16_X + N16_WQ)  { src = (const float4*)wq; dst = (uint4*)wqo; j = i - N16_X; }
    else if (i < N16_X + N16_WQ + N16_WP)
                                  { src = (const float4*)wp; dst = (uint4*)wpo; j = i - N16_X - N16_WQ; }
    else return;
    float4 v0 = src[4 * j], v1 = src[4 * j + 1];
    float4 v2 = src[4 * j + 2], v3 = src[4 * j + 3];
    uint32_t m0 = f2h2(v0.x, v0.y), m1 = f2h2(v0.z, v0.w);
    uint32_t m2 = f2h2(v1.x, v1.y), m3 = f2h2(v1.z, v1.w);
    uint32_t m4 = f2h2(v2.x, v2.y), m5 = f2h2(v2.z, v2.w);
    uint32_t m6 = f2h2(v3.x, v3.y), m7 = f2h2(v3.z, v3.w);
    dst[2 * j]     = make_uint4(m0, m4, m1, m5);
    dst[2 * j + 1] = make_uint4(m2, m6, m3, m7);
}

// ---------------------------------------------------------------------------
// fp16 mma.sync NT GEMM on permuted fp16 inputs.
// half_out=1: write fp16 half2 pairs (natural order), scaling columns
// < qcols by qscale. half_out=0: write fp32.
// ---------------------------------------------------------------------------
#define STAGES 3
#define BKH 32
#define AST32 24
#define STAGE_U32 (128 * AST32 * 2)            // 6144 uint32
#define GEMM_SMEM (STAGES * STAGE_U32 * 4)     // 73728 bytes

__global__ __launch_bounds__(256, 2)
void gemm_mma_kernel(const uint32_t* __restrict__ A, const uint32_t* __restrict__ B,
                     void* __restrict__ Cp, int M, int N, int K,
                     int half_out, float qscale, int qcols)
{
    extern __shared__ uint32_t smu[];
    uint32_t sb = smem_u32(smu);
    const int tid = threadIdx.x;
    const int wid = tid >> 5;
    const int l   = tid & 31;
    const int g   = l >> 2;
    const int tg  = l & 3;
    const int wm  = wid >> 1;
    const int wn  = wid & 1;
    const int m0  = blockIdx.y * 128;
    const int n0  = blockIdx.x * 128;
    const int nchunk = K / BKH;
    const int rs  = K / 2;              // uint32 per gmem row

    auto issue = [&](int c, int s) {
        uint32_t sA = sb + (uint32_t)s * STAGE_U32 * 4;
        uint32_t sB = sA + 128u * AST32 * 4;
        const uint32_t* Ab = A + (size_t)m0 * rs + c * (BKH / 2);
        const uint32_t* Bb = B + (size_t)n0 * rs + c * (BKH / 2);
        #pragma unroll
        for (int i = 0; i < 2; i++) {
            int idx = tid + 256 * i;        // 0..511
            int row = idx >> 2;
            int c4  = idx & 3;
            uint32_t so = (uint32_t)(row * AST32 + c4 * 4) * 4;
            CP_ASYNC16(sA + so, Ab + (size_t)row * rs + c4 * 4);
            CP_ASYNC16(sB + so, Bb + (size_t)row * rs + c4 * 4);
        }
        CP_COMMIT();
    };

    float acc[2][8][4];
    #pragma unroll
    for (int mt = 0; mt < 2; mt++)
        #pragma unroll
        for (int nt = 0; nt < 8; nt++)
            #pragma unroll
            for (int q = 0; q < 4; q++) acc[mt][nt][q] = 0.f;

    issue(0, 0);
    issue(1, 1);

    const int abase = (wm * 32 + g) * AST32 + 2 * tg;
    const int bbase = (wn * 64 + g) * AST32 + 2 * tg;

    for (int c = 0; c < nchunk; c++) {
        if (c == nchunk - 1) { CP_WAIT0(); } else { CP_WAIT1(); }
        __syncthreads();

        int cn = c + 2;
        if (cn < nchunk) issue(cn, cn % STAGES);

        const uint32_t* Au = smu + (size_t)(c % STAGES) * STAGE_U32;
        const uint32_t* Bu = Au + 128 * AST32;

        #pragma unroll
        for (int s = 0; s < 2; s++) {
            uint32_t a[2][4];
            #pragma unroll
            for (int mt = 0; mt < 2; mt++) {
                uint2 lo = *(const uint2*)&Au[abase + mt * 16 * AST32 + s * 8];
                uint2 hi = *(const uint2*)&Au[abase + mt * 16 * AST32 + 8 * AST32 + s * 8];
                a[mt][0] = lo.x; a[mt][2] = lo.y;
                a[mt][1] = hi.x; a[mt][3] = hi.y;
            }
            uint32_t b[8][2];
            #pragma unroll
            for (int nt = 0; nt < 8; nt++) {
                uint2 bv = *(const uint2*)&Bu[bbase + nt * 8 * AST32 + s * 8];
                b[nt][0] = bv.x; b[nt][1] = bv.y;
            }
            #pragma unroll
            for (int mt = 0; mt < 2; mt++)
                #pragma unroll
                for (int nt = 0; nt < 8; nt++)
                    mma_f16(acc[mt][nt][0], acc[mt][nt][1],
                            acc[mt][nt][2], acc[mt][nt][3],
                            a[mt][0], a[mt][1], a[mt][2], a[mt][3],
                            b[nt][0], b[nt][1]);
        }
    }

    if (half_out) {
        uint32_t* Ch = (uint32_t*)Cp;
        const float sc = (n0 < qcols) ? qscale : 1.0f;
        #pragma unroll
        for (int mt = 0; mt < 2; mt++) {
            int r = m0 + wm * 32 + mt * 16 + g;
            #pragma unroll
            for (int nt = 0; nt < 8; nt++) {
                int cc = n0 + wn * 64 + nt * 8 + tg * 2;
                Ch[((size_t)r * N + cc) >> 1] =
                    f2h2(acc[mt][nt][0] * sc, acc[mt][nt][1] * sc);
                Ch[((size_t)(r + 8) * N + cc) >> 1] =
                    f2h2(acc[mt][nt][2] * sc, acc[mt][nt][3] * sc);
            }
        }
    } else {
        float* C = (float*)Cp;
        #pragma unroll
        for (int mt = 0; mt < 2; mt++) {
            int r = m0 + wm * 32 + mt * 16 + g;
            #pragma unroll
            for (int nt = 0; nt < 8; nt++) {
                int cc = n0 + wn * 64 + nt * 8 + tg * 2;
                *(float2*)&C[(size_t)r * N + cc] =
                    make_float2(acc[mt][nt][0], acc[mt][nt][1]);
                *(float2*)&C[(size_t)(r + 8) * N + cc] =
                    make_float2(acc[mt][nt][2], acc[mt][nt][3]);
            }
        }
    }
}

// ---------------------------------------------------------------------------
// Flash attention, all-fp16 MMAs, fp16 qkv input (Q pre-scaled).
// K/V tiles double-buffered via cp.async (copy overlaps previous tile's
// compute). PV: P A-frags from S registers, V B-frags via ldmatrix.x4.trans.
// QTILE=64, 4 CTAs/SM, longest CTAs first. Output: K-pair-permuted fp16.
// ---------------------------------------------------------------------------
#define KST32 36                         // u32 row stride (K and V)
#define QST   36
#define STG_U32 (2 * 64 * KST32)         // K + V per stage = 4608 u32
#define ATT_SMEM (2 * STG_U32 * 4)       // 36864 bytes
#define RS3 (D3z / 2)                    // qkv row stride in u32 = 1536

__global__ __launch_bounds__(128, 4) void attn_mma_kernel(
    const uint32_t* __restrict__ qkv, uint32_t* __restrict__ out)
{
    extern __shared__ uint32_t smu[];
    const uint32_t sb = smem_u32(smu);
    uint32_t* Qs = smu + STG_U32;        // alias: stage-1 region (K part)

    const int tid = threadIdx.x;
    const int w  = tid >> 5;
    const int l  = tid & 31;
    const int g  = l >> 2;
    const int tg = l & 3;
    const int qt = gridDim.x - 1 - blockIdx.x;   // longest work first
    const int h  = blockIdx.y;
    const int b  = blockIdx.z;
    const int q0 = qt * 64;
    const int bS = b * Sz;
    const float NEG_INF = -__int_as_float(0x7f800000);

    // ldmatrix lane byte offset within a V tile (adds stage base per tile)
    const uint32_t vlaneoff =
        ((((l >> 3) & 1) * 8 + (l & 7)) * KST32 + (l >> 4) * 4) * 4u;

    auto issue_tile = [&](int kt, int st) {
        uint32_t dstK = sb + (uint32_t)st * STG_U32 * 4u;
        uint32_t dstV = dstK + 64u * KST32 * 4u;
        const uint32_t* baseK = qkv + (size_t)(bS + kt * 64) * RS3 + 512 + h * 32;
        #pragma unroll
        for (int i = 0; i < 4; i++) {
            int idx = tid + 128 * i;     // 0..511
            int r = idx >> 3, c4 = idx & 7;
            uint32_t so = (uint32_t)(r * KST32 + c4 * 4) * 4u;
            const uint32_t* srcK = baseK + (size_t)r * RS3 + c4 * 4;
            CP_ASYNC16(dstK + so, srcK);
            CP_ASYNC16(dstV + so, srcK + 512);
        }
        CP_COMMIT();
    };

    issue_tile(0, 0);   // overlaps Q staging below

    // Stage Q (already fp16, already scaled) into Qs
    for (int idx = tid; idx < 512; idx += 128) {
        int r = idx >> 3, c4 = idx & 7;
        uint4 v = *(const uint4*)(qkv + (size_t)(bS + q0 + r) * RS3 + h * 32 + c4 * 4);
        *(uint4*)&Qs[r * QST + c4 * 4] = v;
    }
    __syncthreads();

    uint32_t qa[4][4];
    const int qr0 = (w * 16 + g) * QST;
    const int qr1 = qr0 + 8 * QST;
    #pragma unroll
    for (int s = 0; s < 4; s++) {
        qa[s][0] = Qs[qr0 + s * 8 + tg];
        qa[s][1] = Qs[qr1 + s * 8 + tg];
        qa[s][2] = Qs[qr0 + s * 8 + tg + 4];
        qa[s][3] = Qs[qr1 + s * 8 + tg + 4];
    }
    __syncthreads();   // all qa reads done before iter0 overwrites stage 1

    float o[8][4];
    #pragma unroll
    for (int nt = 0; nt < 8; nt++)
        #pragma unroll
        for (int q = 0; q < 4; q++) o[nt][q] = 0.f;
    float m0 = NEG_INF, m1 = NEG_INF, l0 = 0.f, l1 = 0.f;

    for (int kt = 0; kt <= qt; kt++) {
        const int cur = kt & 1;
        if (kt + 1 <= qt) { issue_tile(kt + 1, cur ^ 1); CP_WAIT1(); }
        else              { CP_WAIT0(); }
        __syncthreads();

        const uint32_t* Kh = smu + (size_t)cur * STG_U32;
        const uint32_t vstage = sb + ((uint32_t)cur * STG_U32 + 64u * KST32) * 4u
                                + vlaneoff;

        // Scores S = Q K^T (fp16, 4 k-steps over d)
        float s[8][4];
        #pragma unroll
        for (int nt = 0; nt < 8; nt++)
            #pragma unroll
            for (int q = 0; q < 4; q++) s[nt][q] = 0.f;

        #pragma unroll
        for (int ks = 0; ks < 4; ks++) {
            #pragma unroll
            for (int nt = 0; nt < 8; nt++) {
                int kb = (nt * 8 + g) * KST32 + ks * 8 + tg;
                uint32_t b0 = Kh[kb];
                uint32_t b1 = Kh[kb + 4];
                mma_f16(s[nt][0], s[nt][1], s[nt][2], s[nt][3],
                        qa[ks][0], qa[ks][1], qa[ks][2], qa[ks][3], b0, b1);
            }
        }

        if (kt == qt) {
            int i0 = w * 16 + g, i1 = i0 + 8;
            #pragma unroll
            for (int nt = 0; nt < 8; nt++) {
                int j0 = nt * 8 + 2 * tg;
                if (j0     > i0) s[nt][0] = NEG_INF;
                if (j0 + 1 > i0) s[nt][1] = NEG_INF;
                if (j0     > i1) s[nt][2] = NEG_INF;
                if (j0 + 1 > i1) s[nt][3] = NEG_INF;
            }
        }

        // Online softmax (rows g, g+8; quad-lane reductions)
        float r0 = NEG_INF, r1 = NEG_INF;
        #pragma unroll
        for (int nt = 0; nt < 8; nt++) {
            r0 = fmaxf(r0, fmaxf(s[nt][0], s[nt][1]));
            r1 = fmaxf(r1, fmaxf(s[nt][2], s[nt][3]));
        }
        r0 = fmaxf(r0, __shfl_xor_sync(0xffffffffu, r0, 1));
        r0 = fmaxf(r0, __shfl_xor_sync(0xffffffffu, r0, 2));
        r1 = fmaxf(r1, __shfl_xor_sync(0xffffffffu, r1, 1));
        r1 = fmaxf(r1, __shfl_xor_sync(0xffffffffu, r1, 2));

        float nm0 = fmaxf(m0, r0), nm1 = fmaxf(m1, r1);
        float a0 = __expf(m0 - nm0), a1 = __expf(m1 - nm1);
        float sum0 = 0.f, sum1 = 0.f;
        #pragma unroll
        for (int nt = 0; nt < 8; nt++) {
            s[nt][0] = __expf(s[nt][0] - nm0);
            s[nt][1] = __expf(s[nt][1] - nm0);
            s[nt][2] = __expf(s[nt][2] - nm1);
            s[nt][3] = __expf(s[nt][3] - nm1);
            sum0 += s[nt][0] + s[nt][1];
            sum1 += s[nt][2] + s[nt][3];
        }
        sum0 += __shfl_xor_sync(0xffffffffu, sum0, 1);
        sum0 += __shfl_xor_sync(0xffffffffu, sum0, 2);
        sum1 += __shfl_xor_sync(0xffffffffu, sum1, 1);
        sum1 += __shfl_xor_sync(0xffffffffu, sum1, 2);
        m0 = nm0; m1 = nm1;
        l0 = l0 * a0 + sum0;
        l1 = l1 * a1 + sum1;

        #pragma unroll
        for (int nt = 0; nt < 8; nt++) {
            o[nt][0] *= a0; o[nt][1] *= a0;
            o[nt][2] *= a1; o[nt][3] *= a1;
        }

        // O += P V: P A-frags from s registers; V B-frags via ldmatrix.trans
        #pragma unroll
        for (int ks = 0; ks < 4; ks++) {
            uint32_t pa0 = f2h2(s[2 * ks][0],     s[2 * ks][1]);
            uint32_t pa1 = f2h2(s[2 * ks][2],     s[2 * ks][3]);
            uint32_t pa2 = f2h2(s[2 * ks + 1][0], s[2 * ks + 1][1]);
            uint32_t pa3 = f2h2(s[2 * ks + 1][2], s[2 * ks + 1][3]);
            #pragma unroll
            for (int ntp = 0; ntp < 4; ntp++) {
                uint32_t b0, b1, b2, b3;
                uint32_t addr = vstage + (uint32_t)(ks * 16 * KST32 + ntp * 8) * 4u;
                LDMATRIX_X4_TRANS(b0, b1, b2, b3, addr);
                mma_f16(o[2 * ntp][0],     o[2 * ntp][1],
                        o[2 * ntp][2],     o[2 * ntp][3],
                        pa0, pa1, pa2, pa3, b0, b1);
                mma_f16(o[2 * ntp + 1][0], o[2 * ntp + 1][1],
                        o[2 * ntp + 1][2], o[2 * ntp + 1][3],
                        pa0, pa1, pa2, pa3, b2, b3);
            }
        }
        __syncthreads();   // all reads of stage `cur` done before reuse
    }

    // Epilogue: scale by 1/l, write K-pair-PERMUTED fp16 for the proj GEMM.
    float i0v = 1.f / l0, i1v = 1.f / l1;
    uint32_t* o0p = out + ((size_t)(bS + q0 + w * 16 + g) * Dz + h * HDz) / 2;
    uint32_t* o1p = o0p + (size_t)8 * Dz / 2;
    #pragma unroll
    for (int nt = 0; nt < 8; nt++) {
        int slot = (nt & 1) ? (2 * tg + 1) : (2 * tg);
        int oidx = (nt >> 1) * 8 + slot;
        o0p[oidx] = f2h2(o[nt][0] * i0v, o[nt][1] * i0v);
        o1p[oidx] = f2h2(o[nt][2] * i1v, o[nt][3] * i1v);
    }
}

// ---------------------------------------------------------------------------
extern "C" void kernel_launch(void* const* d_in, const int* in_sizes, int n_in,
                              void* d_out, int out_size)
{
    const float* x      = (const float*)d_in[0];
    const float* w_qkv  = (const float*)d_in[1];
    const float* w_proj = (const float*)d_in[2];
    float* out = (float*)d_out;

    void *qkvp, *attnp, *xp, *wqp, *wpp;
    cudaGetSymbolAddress(&qkvp, g_qkv);
    cudaGetSymbolAddress(&attnp, g_attn);
    cudaGetSymbolAddress(&xp, g_x);
    cudaGetSymbolAddress(&wqp, g_wq);
    cudaGetSymbolAddress(&wpp, g_wp);

    cudaFuncSetAttribute(attn_mma_kernel,
                         cudaFuncAttributeMaxDynamicSharedMemorySize, ATT_SMEM);
    cudaFuncSetAttribute(gemm_mma_kernel,
                         cudaFuncAttributeMaxDynamicSharedMemorySize, GEMM_SMEM);

    const int M = Mz;

    // 0) fp16-convert + K-pair-permute all GEMM inputs
    {
        int total = N16_X + N16_WQ + N16_WP;
        cvt_all_kernel<<<(total + 255) / 256, 256>>>(
            x, (uint32_t*)xp, w_qkv, (uint32_t*)wqp, w_proj, (uint32_t*)wpp);
    }

    // 1) QKV projection -> fp16 qkv (Q columns pre-scaled by 0.125)
    gemm_mma_kernel<<<dim3(D3z / 128, M / 128), 256, GEMM_SMEM>>>(
        (const uint32_t*)xp, (const uint32_t*)wqp, qkvp, M, D3z, Dz,
        1, 0.125f, Dz);

    // 2) Causal flash attention (all-fp16, cp.async double-buffered K/V)
    attn_mma_kernel<<<dim3(Sz / 64, Hz, Bz), 128, ATT_SMEM>>>(
        (const uint32_t*)qkvp, (uint32_t*)attnp);

    // 3) Output projection -> fp32 d_out
    gemm_mma_kernel<<<dim3(Dz / 128, M / 128), 256, GEMM_SMEM>>>(
        (const uint32_t*)attnp, (const uint32_t*)wpp, d_out, M, Dz, Dz,
        0, 1.0f, 0);
}

// round 13
// speedup vs baseline: 1.6243x; 1.0932x over previous
#include <cuda_runtime.h>
#include <cuda_fp16.h>
#include <cstdint>
#include <math.h>

// Problem constants
#define Bz 4
#define Sz 2048
#define Dz 1024
#define Hz 16
#define HDz 64
#define D3z 3072
#define Mz (Bz * Sz)

// Scratch (device globals: allocation-free per harness rules)
// ALL fp16 buffers in NATURAL half2-over-K order. Q in g_qkv pre-scaled 0.125.
__device__ uint32_t g_qkv[(size_t)Mz * D3z / 2];
__device__ uint32_t g_attn[(size_t)Mz * Dz / 2];
__device__ uint32_t g_x  [(size_t)Mz * Dz / 2];
__device__ uint32_t g_wq [(size_t)D3z * Dz / 2];
__device__ uint32_t g_wp [(size_t)Dz * Dz / 2];

// ---------------------------------------------------------------------------
// Helpers
// ---------------------------------------------------------------------------
__device__ __forceinline__ uint32_t smem_u32(const void* p) {
    uint32_t a;
    asm("{ .reg .u64 t; cvta.to.shared.u64 t, %1; cvt.u32.u64 %0, t; }"
        : "=r"(a) : "l"(p));
    return a;
}

__device__ __forceinline__ uint32_t f2h2(float a, float b) {
    __half2 h = __floats2half2_rn(a, b);   // low 16 bits = a
    return *(uint32_t*)&h;
}

#define CP_ASYNC16(dst, src) \
    asm volatile("cp.async.cg.shared.global [%0], [%1], 16;" \
        :: "r"((uint32_t)(dst)), "l"(src) : "memory")
#define CP_COMMIT() asm volatile("cp.async.commit_group;" ::: "memory")
#define CP_WAIT1() asm volatile("cp.async.wait_group 1;" ::: "memory")
#define CP_WAIT0() asm volatile("cp.async.wait_group 0;" ::: "memory")

// m16n8k16 fp16 MMA, fp32 accumulate (sm_80+, valid at compute_103)
__device__ __forceinline__ void mma_f16(
    float& d0, float& d1, float& d2, float& d3,
    uint32_t a0, uint32_t a1, uint32_t a2, uint32_t a3,
    uint32_t b0, uint32_t b1)
{
    asm volatile(
        "mma.sync.aligned.m16n8k16.row.col.f32.f16.f16.f32 "
        "{%0,%1,%2,%3}, {%4,%5,%6,%7}, {%8,%9}, {%0,%1,%2,%3};"
        : "+f"(d0), "+f"(d1), "+f"(d2), "+f"(d3)
        : "r"(a0), "r"(a1), "r"(a2), "r"(a3), "r"(b0), "r"(b1));
}

// ldmatrix x4 (sm_75+, valid at compute_103)
#define LDMATRIX_X4(r0, r1, r2, r3, addr) \
    asm volatile("ldmatrix.sync.aligned.m8n8.x4.shared.b16 " \
        "{%0,%1,%2,%3}, [%4];" \
        : "=r"(r0), "=r"(r1), "=r"(r2), "=r"(r3) : "r"(addr))

#define LDMATRIX_X4_TRANS(r0, r1, r2, r3, addr) \
    asm volatile("ldmatrix.sync.aligned.m8n8.x4.trans.shared.b16 " \
        "{%0,%1,%2,%3}, [%4];" \
        : "=r"(r0), "=r"(r1), "=r"(r2), "=r"(r3) : "r"(addr))

// ---------------------------------------------------------------------------
// Fused fp32 -> fp16 conversion (natural order) over x, w_qkv, w_proj.
// ---------------------------------------------------------------------------
#define N16_X  (Mz * Dz / 16)
#define N16_WQ (D3z * Dz / 16)
#define N16_WP (Dz * Dz / 16)

__global__ __launch_bounds__(256) void cvt_all_kernel(
    const float* __restrict__ x,  uint32_t* __restrict__ xo,
    const float* __restrict__ wq, uint32_t* __restrict__ wqo,
    const float* __restrict__ wp, uint32_t* __restrict__ wpo)
{
    int i = blockIdx.x * blockDim.x + threadIdx.x;
    const float4* src;
    uint4* dst;
    int j;
    if (i < N16_X)                { src = (const float4*)x;  dst = (uint4*)xo;  j = i; }
    else if (i < N16_X + N16_WQ)  { src = (const float4*)wq; dst = (uint4*)wqo; j = i - N16_X; }
    else if (i < N16_X + N16_WQ + N16_WP)
                                  { src = (const float4*)wp; dst = (uint4*)wpo; j = i - N16_X - N16_WQ; }
    else return;
    float4 v0 = src[4 * j], v1 = src[4 * j + 1];
    float4 v2 = src[4 * j + 2], v3 = src[4 * j + 3];
    dst[2 * j]     = make_uint4(f2h2(v0.x, v0.y), f2h2(v0.z, v0.w),
                                f2h2(v1.x, v1.y), f2h2(v1.z, v1.w));
    dst[2 * j + 1] = make_uint4(f2h2(v2.x, v2.y), f2h2(v2.z, v2.w),
                                f2h2(v3.x, v3.y), f2h2(v3.z, v3.w));
}

// ---------------------------------------------------------------------------
// fp16 mma.sync NT GEMM, natural layout, ldmatrix fragment loads.
// 128x128 CTA, BK=32 halves (16 u32), 8 warps (4Mx2N). 3-stage cp.async.
// Row stride 20 u32 (ldmatrix 8-row groups hit distinct banks). 2 CTAs/SM.
// half_out=1: fp16 out, cols < qcols scaled by qscale. K in HALVES.
// ---------------------------------------------------------------------------
#define STAGES 3
#define BKH 32
#define AST32 20
#define STAGE_U32 (128 * AST32 * 2)            // 5120 u32
#define GEMM_SMEM (STAGES * STAGE_U32 * 4)     // 61440 bytes

__global__ __launch_bounds__(256, 2)
void gemm_mma_kernel(const uint32_t* __restrict__ A, const uint32_t* __restrict__ B,
                     void* __restrict__ Cp, int M, int N, int K,
                     int half_out, float qscale, int qcols)
{
    extern __shared__ uint32_t smu[];
    uint32_t sb = smem_u32(smu);
    const int tid = threadIdx.x;
    const int wid = tid >> 5;
    const int l   = tid & 31;
    const int g   = l >> 2;
    const int tg  = l & 3;
    const int wm  = wid >> 1;
    const int wn  = wid & 1;
    const int m0  = blockIdx.y * 128;
    const int n0  = blockIdx.x * 128;
    const int nchunk = K / BKH;
    const int rs  = K / 2;              // u32 per gmem row

    auto issue = [&](int c, int s) {
        uint32_t sA = sb + (uint32_t)s * STAGE_U32 * 4;
        uint32_t sB = sA + 128u * AST32 * 4;
        const uint32_t* Ab = A + (size_t)m0 * rs + c * (BKH / 2);
        const uint32_t* Bb = B + (size_t)n0 * rs + c * (BKH / 2);
        #pragma unroll
        for (int i = 0; i < 2; i++) {
            int idx = tid + 256 * i;        // 0..511
            int row = idx >> 2;
            int c4  = idx & 3;
            uint32_t so = (uint32_t)(row * AST32 + c4 * 4) * 4;
            CP_ASYNC16(sA + so, Ab + (size_t)row * rs + c4 * 4);
            CP_ASYNC16(sB + so, Bb + (size_t)row * rs + c4 * 4);
        }
        CP_COMMIT();
    };

    float acc[2][8][4];
    #pragma unroll
    for (int mt = 0; mt < 2; mt++)
        #pragma unroll
        for (int nt = 0; nt < 8; nt++)
            #pragma unroll
            for (int q = 0; q < 4; q++) acc[mt][nt][q] = 0.f;

    issue(0, 0);
    issue(1, 1);

    // ldmatrix lane byte offsets
    // A (16x16 block): mat0 rows0-7/k0-7, mat1 rows8-15/k0-7, mat2/3 = k8-15
    const uint32_t a_lane =
        ((uint32_t)((wm * 32 + ((l >> 3) & 1) * 8 + (l & 7)) * AST32
                    + (l >> 4) * 4)) * 4u;
    // B (2 n-tiles x 16k): mat0 ntA/k0-7, mat1 ntA/k8-15, mat2/3 = ntB
    const uint32_t b_lane =
        ((uint32_t)((wn * 64 + (l >> 4) * 8 + (l & 7)) * AST32
                    + ((l >> 3) & 1) * 4)) * 4u;

    for (int c = 0; c < nchunk; c++) {
        if (c == nchunk - 1) { CP_WAIT0(); } else { CP_WAIT1(); }
        __syncthreads();

        int cn = c + 2;
        if (cn < nchunk) issue(cn, cn % STAGES);

        const uint32_t stg = sb + (uint32_t)(c % STAGES) * STAGE_U32 * 4;
        const uint32_t stgB = stg + 128u * AST32 * 4;

        #pragma unroll
        for (int s = 0; s < 2; s++) {       // two k16-steps per chunk
            uint32_t a[2][4];
            #pragma unroll
            for (int mt = 0; mt < 2; mt++) {
                uint32_t addr = stg + a_lane
                    + (uint32_t)(mt * 16 * AST32 + s * 8) * 4u;
                LDMATRIX_X4(a[mt][0], a[mt][1], a[mt][2], a[mt][3], addr);
            }
            uint32_t b[8][2];
            #pragma unroll
            for (int ntp = 0; ntp < 4; ntp++) {
                uint32_t addr = stgB + b_lane
                    + (uint32_t)(ntp * 16 * AST32 + s * 8) * 4u;
                LDMATRIX_X4(b[2 * ntp][0], b[2 * ntp][1],
                            b[2 * ntp + 1][0], b[2 * ntp + 1][1], addr);
            }
            #pragma unroll
            for (int mt = 0; mt < 2; mt++)
                #pragma unroll
                for (int nt = 0; nt < 8; nt++)
                    mma_f16(acc[mt][nt][0], acc[mt][nt][1],
                            acc[mt][nt][2], acc[mt][nt][3],
                            a[mt][0], a[mt][1], a[mt][2], a[mt][3],
                            b[nt][0], b[nt][1]);
        }
    }

    if (half_out) {
        uint32_t* Ch = (uint32_t*)Cp;
        const float sc = (n0 < qcols) ? qscale : 1.0f;
        #pragma unroll
        for (int mt = 0; mt < 2; mt++) {
            int r = m0 + wm * 32 + mt * 16 + g;
            #pragma unroll
            for (int nt = 0; nt < 8; nt++) {
                int cc = n0 + wn * 64 + nt * 8 + tg * 2;
                Ch[((size_t)r * N + cc) >> 1] =
                    f2h2(acc[mt][nt][0] * sc, acc[mt][nt][1] * sc);
                Ch[((size_t)(r + 8) * N + cc) >> 1] =
                    f2h2(acc[mt][nt][2] * sc, acc[mt][nt][3] * sc);
            }
        }
    } else {
        float* C = (float*)Cp;
        #pragma unroll
        for (int mt = 0; mt < 2; mt++) {
            int r = m0 + wm * 32 + mt * 16 + g;
            #pragma unroll
            for (int nt = 0; nt < 8; nt++) {
                int cc = n0 + wn * 64 + nt * 8 + tg * 2;
                *(float2*)&C[(size_t)r * N + cc] =
                    make_float2(acc[mt][nt][0], acc[mt][nt][1]);
                *(float2*)&C[(size_t)(r + 8) * N + cc] =
                    make_float2(acc[mt][nt][2], acc[mt][nt][3]);
            }
        }
    }
}

// ---------------------------------------------------------------------------
// Flash attention, all-fp16 MMAs, all fragment loads via ldmatrix.
// K/V double-buffered cp.async; PV uses S-register P + ldmatrix.trans V.
// QTILE=64, 4 CTAs/SM, longest CTAs first. Output natural fp16.
// ---------------------------------------------------------------------------
#define KST32 36                         // u32 row stride (K, V, Q staging)
#define QST   36
#define STG_U32 (2 * 64 * KST32)         // K + V per stage = 4608 u32
#define ATT_SMEM (2 * STG_U32 * 4)       // 36864 bytes
#define RS3 (D3z / 2)                    // qkv row stride in u32

__global__ __launch_bounds__(128, 4) void attn_mma_kernel(
    const uint32_t* __restrict__ qkv, uint32_t* __restrict__ out)
{
    extern __shared__ uint32_t smu[];
    const uint32_t sb = smem_u32(smu);
    uint32_t* Qs = smu + STG_U32;        // alias: stage-1 region

    const int tid = threadIdx.x;
    const int w  = tid >> 5;
    const int l  = tid & 31;
    const int g  = l >> 2;
    const int tg = l & 3;
    const int qt = gridDim.x - 1 - blockIdx.x;   // longest work first
    const int h  = blockIdx.y;
    const int b  = blockIdx.z;
    const int q0 = qt * 64;
    const int bS = b * Sz;
    const float NEG_INF = -__int_as_float(0x7f800000);

    // ldmatrix lane byte offsets
    const uint32_t vlaneoff =   // V trans (R11-proven)
        ((((l >> 3) & 1) * 8 + (l & 7)) * KST32 + (l >> 4) * 4) * 4u;
    const uint32_t klaneoff =   // K non-trans B-frags (2 n-tiles per x4)
        (((l >> 4) * 8 + (l & 7)) * KST32 + ((l >> 3) & 1) * 4) * 4u;
    const uint32_t qlaneoff =   // Q non-trans A-frags (16x16 block)
        ((uint32_t)((w * 16 + ((l >> 3) & 1) * 8 + (l & 7)) * QST
                    + (l >> 4) * 4)) * 4u;

    auto issue_tile = [&](int kt, int st) {
        uint32_t dstK = sb + (uint32_t)st * STG_U32 * 4u;
        uint32_t dstV = dstK + 64u * KST32 * 4u;
        const uint32_t* baseK = qkv + (size_t)(bS + kt * 64) * RS3 + 512 + h * 32;
        #pragma unroll
        for (int i = 0; i < 4; i++) {
            int idx = tid + 128 * i;     // 0..511
            int r = idx >> 3, c4 = idx & 7;
            uint32_t so = (uint32_t)(r * KST32 + c4 * 4) * 4u;
            const uint32_t* srcK = baseK + (size_t)r * RS3 + c4 * 4;
            CP_ASYNC16(dstK + so, srcK);
            CP_ASYNC16(dstV + so, srcK + 512);
        }
        CP_COMMIT();
    };

    issue_tile(0, 0);   // overlaps Q staging below

    // Stage Q (fp16, pre-scaled) into Qs
    for (int idx = tid; idx < 512; idx += 128) {
        int r = idx >> 3, c4 = idx & 7;
        uint4 v = *(const uint4*)(qkv + (size_t)(bS + q0 + r) * RS3 + h * 32 + c4 * 4);
        *(uint4*)&Qs[r * QST + c4 * 4] = v;
    }
    __syncthreads();

    uint32_t qa[4][4];
    {
        const uint32_t qbase = sb + STG_U32 * 4u + qlaneoff;
        #pragma unroll
        for (int ks = 0; ks < 4; ks++)
            LDMATRIX_X4(qa[ks][0], qa[ks][1], qa[ks][2], qa[ks][3],
                        qbase + (uint32_t)(ks * 8) * 4u);
    }
    __syncthreads();   // qa reads done before iter0 overwrites stage 1

    float o[8][4];
    #pragma unroll
    for (int nt = 0; nt < 8; nt++)
        #pragma unroll
        for (int q = 0; q < 4; q++) o[nt][q] = 0.f;
    float m0 = NEG_INF, m1 = NEG_INF, l0 = 0.f, l1 = 0.f;

    for (int kt = 0; kt <= qt; kt++) {
        const int cur = kt & 1;
        if (kt + 1 <= qt) { issue_tile(kt + 1, cur ^ 1); CP_WAIT1(); }
        else              { CP_WAIT0(); }
        __syncthreads();

        const uint32_t kstage = sb + (uint32_t)cur * STG_U32 * 4u + klaneoff;
        const uint32_t vstage = sb + ((uint32_t)cur * STG_U32 + 64u * KST32) * 4u
                                + vlaneoff;

        // Scores S = Q K^T (fp16, 4 k-steps over d)
        float s[8][4];
        #pragma unroll
        for (int nt = 0; nt < 8; nt++)
            #pragma unroll
            for (int q = 0; q < 4; q++) s[nt][q] = 0.f;

        #pragma unroll
        for (int ks = 0; ks < 4; ks++) {
            #pragma unroll
            for (int ntp = 0; ntp < 4; ntp++) {
                uint32_t b0, b1, b2, b3;
                uint32_t addr = kstage + (uint32_t)(ntp * 16 * KST32 + ks * 8) * 4u;
                LDMATRIX_X4(b0, b1, b2, b3, addr);
                mma_f16(s[2 * ntp][0], s[2 * ntp][1],
                        s[2 * ntp][2], s[2 * ntp][3],
                        qa[ks][0], qa[ks][1], qa[ks][2], qa[ks][3], b0, b1);
                mma_f16(s[2 * ntp + 1][0], s[2 * ntp + 1][1],
                        s[2 * ntp + 1][2], s[2 * ntp + 1][3],
                        qa[ks][0], qa[ks][1], qa[ks][2], qa[ks][3], b2, b3);
            }
        }

        if (kt == qt) {
            int i0 = w * 16 + g, i1 = i0 + 8;
            #pragma unroll
            for (int nt = 0; nt < 8; nt++) {
                int j0 = nt * 8 + 2 * tg;
                if (j0     > i0) s[nt][0] = NEG_INF;
                if (j0 + 1 > i0) s[nt][1] = NEG_INF;
                if (j0     > i1) s[nt][2] = NEG_INF;
                if (j0 + 1 > i1) s[nt][3] = NEG_INF;
            }
        }

        // Online softmax (rows g, g+8; quad-lane reductions)
        float r0 = NEG_INF, r1 = NEG_INF;
        #pragma unroll
        for (int nt = 0; nt < 8; nt++) {
            r0 = fmaxf(r0, fmaxf(s[nt][0], s[nt][1]));
            r1 = fmaxf(r1, fmaxf(s[nt][2], s[nt][3]));
        }
        r0 = fmaxf(r0, __shfl_xor_sync(0xffffffffu, r0, 1));
        r0 = fmaxf(r0, __shfl_xor_sync(0xffffffffu, r0, 2));
        r1 = fmaxf(r1, __shfl_xor_sync(0xffffffffu, r1, 1));
        r1 = fmaxf(r1, __shfl_xor_sync(0xffffffffu, r1, 2));

        float nm0 = fmaxf(m0, r0), nm1 = fmaxf(m1, r1);
        float a0 = __expf(m0 - nm0), a1 = __expf(m1 - nm1);
        float sum0 = 0.f, sum1 = 0.f;
        #pragma unroll
        for (int nt = 0; nt < 8; nt++) {
            s[nt][0] = __expf(s[nt][0] - nm0);
            s[nt][1] = __expf(s[nt][1] - nm0);
            s[nt][2] = __expf(s[nt][2] - nm1);
            s[nt][3] = __expf(s[nt][3] - nm1);
            sum0 += s[nt][0] + s[nt][1];
            sum1 += s[nt][2] + s[nt][3];
        }
        sum0 += __shfl_xor_sync(0xffffffffu, sum0, 1);
        sum0 += __shfl_xor_sync(0xffffffffu, sum0, 2);
        sum1 += __shfl_xor_sync(0xffffffffu, sum1, 1);
        sum1 += __shfl_xor_sync(0xffffffffu, sum1, 2);
        m0 = nm0; m1 = nm1;
        l0 = l0 * a0 + sum0;
        l1 = l1 * a1 + sum1;

        #pragma unroll
        for (int nt = 0; nt < 8; nt++) {
            o[nt][0] *= a0; o[nt][1] *= a0;
            o[nt][2] *= a1; o[nt][3] *= a1;
        }

        // O += P V: P A-frags from s registers; V B-frags via ldmatrix.trans
        #pragma unroll
        for (int ks = 0; ks < 4; ks++) {
            uint32_t pa0 = f2h2(s[2 * ks][0],     s[2 * ks][1]);
            uint32_t pa1 = f2h2(s[2 * ks][2],     s[2 * ks][3]);
            uint32_t pa2 = f2h2(s[2 * ks + 1][0], s[2 * ks + 1][1]);
            uint32_t pa3 = f2h2(s[2 * ks + 1][2], s[2 * ks + 1][3]);
            #pragma unroll
            for (int ntp = 0; ntp < 4; ntp++) {
                uint32_t b0, b1, b2, b3;
                uint32_t addr = vstage + (uint32_t)(ks * 16 * KST32 + ntp * 8) * 4u;
                LDMATRIX_X4_TRANS(b0, b1, b2, b3, addr);
                mma_f16(o[2 * ntp][0],     o[2 * ntp][1],
                        o[2 * ntp][2],     o[2 * ntp][3],
                        pa0, pa1, pa2, pa3, b0, b1);
                mma_f16(o[2 * ntp + 1][0], o[2 * ntp + 1][1],
                        o[2 * ntp + 1][2], o[2 * ntp + 1][3],
                        pa0, pa1, pa2, pa3, b2, b3);
            }
        }
        __syncthreads();   // all reads of stage `cur` done before reuse
    }

    // Epilogue: scale by 1/l, write NATURAL fp16 for the proj GEMM.
    float i0v = 1.f / l0, i1v = 1.f / l1;
    uint32_t* o0p = out + ((size_t)(bS + q0 + w * 16 + g) * Dz + h * HDz) / 2;
    uint32_t* o1p = o0p + (size_t)8 * Dz / 2;
    #pragma unroll
    for (int nt = 0; nt < 8; nt++) {
        int oidx = nt * 4 + tg;
        o0p[oidx] = f2h2(o[nt][0] * i0v, o[nt][1] * i0v);
        o1p[oidx] = f2h2(o[nt][2] * i1v, o[nt][3] * i1v);
    }
}

// ---------------------------------------------------------------------------
extern "C" void kernel_launch(void* const* d_in, const int* in_sizes, int n_in,
                              void* d_out, int out_size)
{
    const float* x      = (const float*)d_in[0];
    const float* w_qkv  = (const float*)d_in[1];
    const float* w_proj = (const float*)d_in[2];

    void *qkvp, *attnp, *xp, *wqp, *wpp;
    cudaGetSymbolAddress(&qkvp, g_qkv);
    cudaGetSymbolAddress(&attnp, g_attn);
    cudaGetSymbolAddress(&xp, g_x);
    cudaGetSymbolAddress(&wqp, g_wq);
    cudaGetSymbolAddress(&wpp, g_wp);

    cudaFuncSetAttribute(attn_mma_kernel,
                         cudaFuncAttributeMaxDynamicSharedMemorySize, ATT_SMEM);
    cudaFuncSetAttribute(gemm_mma_kernel,
                         cudaFuncAttributeMaxDynamicSharedMemorySize, GEMM_SMEM);

    const int M = Mz;

    // 0) fp16-convert all GEMM inputs (natural order)
    {
        int total = N16_X + N16_WQ + N16_WP;
        cvt_all_kernel<<<(total + 255) / 256, 256>>>(
            x, (uint32_t*)xp, w_qkv, (uint32_t*)wqp, w_proj, (uint32_t*)wpp);
    }

    // 1) QKV projection -> fp16 qkv (Q columns pre-scaled by 0.125)
    gemm_mma_kernel<<<dim3(D3z / 128, M / 128), 256, GEMM_SMEM>>>(
        (const uint32_t*)xp, (const uint32_t*)wqp, qkvp, M, D3z, Dz,
        1, 0.125f, Dz);

    // 2) Causal flash attention (all-fp16, ldmatrix everywhere)
    attn_mma_kernel<<<dim3(Sz / 64, Hz, Bz), 128, ATT_SMEM>>>(
        (const uint32_t*)qkvp, (uint32_t*)attnp);

    // 3) Output projection -> fp32 d_out
    gemm_mma_kernel<<<dim3(Dz / 128, M / 128), 256, GEMM_SMEM>>>(
        (const uint32_t*)attnp, (const uint32_t*)wpp, d_out, M, Dz, Dz,
        0, 1.0f, 0);
}

// round 14
// speedup vs baseline: 1.7276x; 1.0635x over previous
#include <cuda_runtime.h>
#include <cuda_fp16.h>
#include <cstdint>
#include <math.h>

// Problem constants
#define Bz 4
#define Sz 2048
#define Dz 1024
#define Hz 16
#define HDz 64
#define D3z 3072
#define Mz (Bz * Sz)

// Scratch (device globals: allocation-free per harness rules)
// ALL fp16 buffers in NATURAL half2-over-K order. Q in g_qkv pre-scaled 0.125.
__device__ uint32_t g_qkv[(size_t)Mz * D3z / 2];
__device__ uint32_t g_attn[(size_t)Mz * Dz / 2];
__device__ uint32_t g_x  [(size_t)Mz * Dz / 2];
__device__ uint32_t g_wq [(size_t)D3z * Dz / 2];
__device__ uint32_t g_wp [(size_t)Dz * Dz / 2];

// ---------------------------------------------------------------------------
// Helpers
// ---------------------------------------------------------------------------
__device__ __forceinline__ uint32_t smem_u32(const void* p) {
    uint32_t a;
    asm("{ .reg .u64 t; cvta.to.shared.u64 t, %1; cvt.u32.u64 %0, t; }"
        : "=r"(a) : "l"(p));
    return a;
}

__device__ __forceinline__ uint32_t f2h2(float a, float b) {
    __half2 h = __floats2half2_rn(a, b);   // low 16 bits = a
    return *(uint32_t*)&h;
}

#define CP_ASYNC16(dst, src) \
    asm volatile("cp.async.cg.shared.global [%0], [%1], 16;" \
        :: "r"((uint32_t)(dst)), "l"(src) : "memory")
#define CP_COMMIT() asm volatile("cp.async.commit_group;" ::: "memory")
#define CP_WAIT1() asm volatile("cp.async.wait_group 1;" ::: "memory")
#define CP_WAIT0() asm volatile("cp.async.wait_group 0;" ::: "memory")

// m16n8k16 fp16 MMA, fp32 accumulate (sm_80+, valid at compute_103)
__device__ __forceinline__ void mma_f16(
    float& d0, float& d1, float& d2, float& d3,
    uint32_t a0, uint32_t a1, uint32_t a2, uint32_t a3,
    uint32_t b0, uint32_t b1)
{
    asm volatile(
        "mma.sync.aligned.m16n8k16.row.col.f32.f16.f16.f32 "
        "{%0,%1,%2,%3}, {%4,%5,%6,%7}, {%8,%9}, {%0,%1,%2,%3};"
        : "+f"(d0), "+f"(d1), "+f"(d2), "+f"(d3)
        : "r"(a0), "r"(a1), "r"(a2), "r"(a3), "r"(b0), "r"(b1));
}

// ldmatrix x4 (sm_75+, valid at compute_103)
#define LDMATRIX_X4(r0, r1, r2, r3, addr) \
    asm volatile("ldmatrix.sync.aligned.m8n8.x4.shared.b16 " \
        "{%0,%1,%2,%3}, [%4];" \
        : "=r"(r0), "=r"(r1), "=r"(r2), "=r"(r3) : "r"(addr))

#define LDMATRIX_X4_TRANS(r0, r1, r2, r3, addr) \
    asm volatile("ldmatrix.sync.aligned.m8n8.x4.trans.shared.b16 " \
        "{%0,%1,%2,%3}, [%4];" \
        : "=r"(r0), "=r"(r1), "=r"(r2), "=r"(r3) : "r"(addr))

// ---------------------------------------------------------------------------
// Fused fp32 -> fp16 conversion (natural order) over x, w_qkv, w_proj.
// ---------------------------------------------------------------------------
#define N16_X  (Mz * Dz / 16)
#define N16_WQ (D3z * Dz / 16)
#define N16_WP (Dz * Dz / 16)

__global__ __launch_bounds__(256) void cvt_all_kernel(
    const float* __restrict__ x,  uint32_t* __restrict__ xo,
    const float* __restrict__ wq, uint32_t* __restrict__ wqo,
    const float* __restrict__ wp, uint32_t* __restrict__ wpo)
{
    int i = blockIdx.x * blockDim.x + threadIdx.x;
    const float4* src;
    uint4* dst;
    int j;
    if (i < N16_X)                { src = (const float4*)x;  dst = (uint4*)xo;  j = i; }
    else if (i < N16_X + N16_WQ)  { src = (const float4*)wq; dst = (uint4*)wqo; j = i - N16_X; }
    else if (i < N16_X + N16_WQ + N16_WP)
                                  { src = (const float4*)wp; dst = (uint4*)wpo; j = i - N16_X - N16_WQ; }
    else return;
    float4 v0 = src[4 * j], v1 = src[4 * j + 1];
    float4 v2 = src[4 * j + 2], v3 = src[4 * j + 3];
    dst[2 * j]     = make_uint4(f2h2(v0.x, v0.y), f2h2(v0.z, v0.w),
                                f2h2(v1.x, v1.y), f2h2(v1.z, v1.w));
    dst[2 * j + 1] = make_uint4(f2h2(v2.x, v2.y), f2h2(v2.z, v2.w),
                                f2h2(v3.x, v3.y), f2h2(v3.z, v3.w));
}

// ---------------------------------------------------------------------------
// fp16 mma.sync NT GEMM, natural layout, ldmatrix fragment loads.
// 128x128 CTA, BK=64 halves, 8 warps (4Mx2N). 2-stage cp.async with ONE
// barrier per chunk (16 barriers total). Row stride 36 u32. 2 CTAs/SM.
// half_out=1: fp16 out, cols < qcols scaled by qscale. K in HALVES.
// ---------------------------------------------------------------------------
#define STAGES 2
#define BKH 64
#define AST32 36
#define STAGE_U32 (128 * AST32 * 2)            // 9216 u32
#define GEMM_SMEM (STAGES * STAGE_U32 * 4)     // 73728 bytes

__global__ __launch_bounds__(256, 2)
void gemm_mma_kernel(const uint32_t* __restrict__ A, const uint32_t* __restrict__ B,
                     void* __restrict__ Cp, int M, int N, int K,
                     int half_out, float qscale, int qcols)
{
    extern __shared__ uint32_t smu[];
    uint32_t sb = smem_u32(smu);
    const int tid = threadIdx.x;
    const int wid = tid >> 5;
    const int l   = tid & 31;
    const int g   = l >> 2;
    const int tg  = l & 3;
    const int wm  = wid >> 1;
    const int wn  = wid & 1;
    const int m0  = blockIdx.y * 128;
    const int n0  = blockIdx.x * 128;
    const int nchunk = K / BKH;
    const int rs  = K / 2;              // u32 per gmem row

    auto issue = [&](int c, int s) {
        uint32_t sA = sb + (uint32_t)s * STAGE_U32 * 4;
        uint32_t sB = sA + 128u * AST32 * 4;
        const uint32_t* Ab = A + (size_t)m0 * rs + c * (BKH / 2);
        const uint32_t* Bb = B + (size_t)n0 * rs + c * (BKH / 2);
        #pragma unroll
        for (int i = 0; i < 4; i++) {
            int idx = tid + 256 * i;        // 0..1023
            int row = idx >> 3;
            int c4  = idx & 7;
            uint32_t so = (uint32_t)(row * AST32 + c4 * 4) * 4;
            CP_ASYNC16(sA + so, Ab + (size_t)row * rs + c4 * 4);
            CP_ASYNC16(sB + so, Bb + (size_t)row * rs + c4 * 4);
        }
        CP_COMMIT();
    };

    float acc[2][8][4];
    #pragma unroll
    for (int mt = 0; mt < 2; mt++)
        #pragma unroll
        for (int nt = 0; nt < 8; nt++)
            #pragma unroll
            for (int q = 0; q < 4; q++) acc[mt][nt][q] = 0.f;

    issue(0, 0);

    // ldmatrix lane byte offsets
    const uint32_t a_lane =
        ((uint32_t)((wm * 32 + ((l >> 3) & 1) * 8 + (l & 7)) * AST32
                    + (l >> 4) * 4)) * 4u;
    const uint32_t b_lane =
        ((uint32_t)((wn * 64 + (l >> 4) * 8 + (l & 7)) * AST32
                    + ((l >> 3) & 1) * 4)) * 4u;

    for (int c = 0; c < nchunk; c++) {
        CP_WAIT0();          // chunk c (sole pending group) has arrived
        __syncthreads();     // visibility + prior-stage reads complete
        if (c + 1 < nchunk) issue(c + 1, (c + 1) & 1);

        const uint32_t stg = sb + (uint32_t)(c & 1) * STAGE_U32 * 4;
        const uint32_t stgB = stg + 128u * AST32 * 4;

        #pragma unroll
        for (int s = 0; s < 4; s++) {       // four k16-steps per chunk
            uint32_t a[2][4];
            #pragma unroll
            for (int mt = 0; mt < 2; mt++) {
                uint32_t addr = stg + a_lane
                    + (uint32_t)(mt * 16 * AST32 + s * 8) * 4u;
                LDMATRIX_X4(a[mt][0], a[mt][1], a[mt][2], a[mt][3], addr);
            }
            uint32_t b[8][2];
            #pragma unroll
            for (int ntp = 0; ntp < 4; ntp++) {
                uint32_t addr = stgB + b_lane
                    + (uint32_t)(ntp * 16 * AST32 + s * 8) * 4u;
                LDMATRIX_X4(b[2 * ntp][0], b[2 * ntp][1],
                            b[2 * ntp + 1][0], b[2 * ntp + 1][1], addr);
            }
            #pragma unroll
            for (int mt = 0; mt < 2; mt++)
                #pragma unroll
                for (int nt = 0; nt < 8; nt++)
                    mma_f16(acc[mt][nt][0], acc[mt][nt][1],
                            acc[mt][nt][2], acc[mt][nt][3],
                            a[mt][0], a[mt][1], a[mt][2], a[mt][3],
                            b[nt][0], b[nt][1]);
        }
    }

    if (half_out) {
        uint32_t* Ch = (uint32_t*)Cp;
        const float sc = (n0 < qcols) ? qscale : 1.0f;
        #pragma unroll
        for (int mt = 0; mt < 2; mt++) {
            int r = m0 + wm * 32 + mt * 16 + g;
            #pragma unroll
            for (int nt = 0; nt < 8; nt++) {
                int cc = n0 + wn * 64 + nt * 8 + tg * 2;
                Ch[((size_t)r * N + cc) >> 1] =
                    f2h2(acc[mt][nt][0] * sc, acc[mt][nt][1] * sc);
                Ch[((size_t)(r + 8) * N + cc) >> 1] =
                    f2h2(acc[mt][nt][2] * sc, acc[mt][nt][3] * sc);
            }
        }
    } else {
        float* C = (float*)Cp;
        #pragma unroll
        for (int mt = 0; mt < 2; mt++) {
            int r = m0 + wm * 32 + mt * 16 + g;
            #pragma unroll
            for (int nt = 0; nt < 8; nt++) {
                int cc = n0 + wn * 64 + nt * 8 + tg * 2;
                *(float2*)&C[(size_t)r * N + cc] =
                    make_float2(acc[mt][nt][0], acc[mt][nt][1]);
                *(float2*)&C[(size_t)(r + 8) * N + cc] =
                    make_float2(acc[mt][nt][2], acc[mt][nt][3]);
            }
        }
    }
}

// ---------------------------------------------------------------------------
// Flash attention, all-fp16 MMAs, all fragment loads via ldmatrix.
// K/V double-buffered cp.async; PV uses S-register P + ldmatrix.trans V.
// QTILE=64, 4 CTAs/SM, longest CTAs first. Output natural fp16.
// (Unchanged from R13 — passed at 4.887e-4.)
// ---------------------------------------------------------------------------
#define KST32 36
#define QST   36
#define STG_U32 (2 * 64 * KST32)
#define ATT_SMEM (2 * STG_U32 * 4)       // 36864 bytes
#define RS3 (D3z / 2)

__global__ __launch_bounds__(128, 4) void attn_mma_kernel(
    const uint32_t* __restrict__ qkv, uint32_t* __restrict__ out)
{
    extern __shared__ uint32_t smu[];
    const uint32_t sb = smem_u32(smu);
    uint32_t* Qs = smu + STG_U32;

    const int tid = threadIdx.x;
    const int w  = tid >> 5;
    const int l  = tid & 31;
    const int g  = l >> 2;
    const int tg = l & 3;
    const int qt = gridDim.x - 1 - blockIdx.x;
    const int h  = blockIdx.y;
    const int b  = blockIdx.z;
    const int q0 = qt * 64;
    const int bS = b * Sz;
    const float NEG_INF = -__int_as_float(0x7f800000);

    const uint32_t vlaneoff =
        ((((l >> 3) & 1) * 8 + (l & 7)) * KST32 + (l >> 4) * 4) * 4u;
    const uint32_t klaneoff =
        (((l >> 4) * 8 + (l & 7)) * KST32 + ((l >> 3) & 1) * 4) * 4u;
    const uint32_t qlaneoff =
        ((uint32_t)((w * 16 + ((l >> 3) & 1) * 8 + (l & 7)) * QST
                    + (l >> 4) * 4)) * 4u;

    auto issue_tile = [&](int kt, int st) {
        uint32_t dstK = sb + (uint32_t)st * STG_U32 * 4u;
        uint32_t dstV = dstK + 64u * KST32 * 4u;
        const uint32_t* baseK = qkv + (size_t)(bS + kt * 64) * RS3 + 512 + h * 32;
        #pragma unroll
        for (int i = 0; i < 4; i++) {
            int idx = tid + 128 * i;
            int r = idx >> 3, c4 = idx & 7;
            uint32_t so = (uint32_t)(r * KST32 + c4 * 4) * 4u;
            const uint32_t* srcK = baseK + (size_t)r * RS3 + c4 * 4;
            CP_ASYNC16(dstK + so, srcK);
            CP_ASYNC16(dstV + so, srcK + 512);
        }
        CP_COMMIT();
    };

    issue_tile(0, 0);

    for (int idx = tid; idx < 512; idx += 128) {
        int r = idx >> 3, c4 = idx & 7;
        uint4 v = *(const uint4*)(qkv + (size_t)(bS + q0 + r) * RS3 + h * 32 + c4 * 4);
        *(uint4*)&Qs[r * QST + c4 * 4] = v;
    }
    __syncthreads();

    uint32_t qa[4][4];
    {
        const uint32_t qbase = sb + STG_U32 * 4u + qlaneoff;
        #pragma unroll
        for (int ks = 0; ks < 4; ks++)
            LDMATRIX_X4(qa[ks][0], qa[ks][1], qa[ks][2], qa[ks][3],
                        qbase + (uint32_t)(ks * 8) * 4u);
    }
    __syncthreads();

    float o[8][4];
    #pragma unroll
    for (int nt = 0; nt < 8; nt++)
        #pragma unroll
        for (int q = 0; q < 4; q++) o[nt][q] = 0.f;
    float m0 = NEG_INF, m1 = NEG_INF, l0 = 0.f, l1 = 0.f;

    for (int kt = 0; kt <= qt; kt++) {
        const int cur = kt & 1;
        if (kt + 1 <= qt) { issue_tile(kt + 1, cur ^ 1); CP_WAIT1(); }
        else              { CP_WAIT0(); }
        __syncthreads();

        const uint32_t kstage = sb + (uint32_t)cur * STG_U32 * 4u + klaneoff;
        const uint32_t vstage = sb + ((uint32_t)cur * STG_U32 + 64u * KST32) * 4u
                                + vlaneoff;

        float s[8][4];
        #pragma unroll
        for (int nt = 0; nt < 8; nt++)
            #pragma unroll
            for (int q = 0; q < 4; q++) s[nt][q] = 0.f;

        #pragma unroll
        for (int ks = 0; ks < 4; ks++) {
            #pragma unroll
            for (int ntp = 0; ntp < 4; ntp++) {
                uint32_t b0, b1, b2, b3;
                uint32_t addr = kstage + (uint32_t)(ntp * 16 * KST32 + ks * 8) * 4u;
                LDMATRIX_X4(b0, b1, b2, b3, addr);
                mma_f16(s[2 * ntp][0], s[2 * ntp][1],
                        s[2 * ntp][2], s[2 * ntp][3],
                        qa[ks][0], qa[ks][1], qa[ks][2], qa[ks][3], b0, b1);
                mma_f16(s[2 * ntp + 1][0], s[2 * ntp + 1][1],
                        s[2 * ntp + 1][2], s[2 * ntp + 1][3],
                        qa[ks][0], qa[ks][1], qa[ks][2], qa[ks][3], b2, b3);
            }
        }

        if (kt == qt) {
            int i0 = w * 16 + g, i1 = i0 + 8;
            #pragma unroll
            for (int nt = 0; nt < 8; nt++) {
                int j0 = nt * 8 + 2 * tg;
                if (j0     > i0) s[nt][0] = NEG_INF;
                if (j0 + 1 > i0) s[nt][1] = NEG_INF;
                if (j0     > i1) s[nt][2] = NEG_INF;
                if (j0 + 1 > i1) s[nt][3] = NEG_INF;
            }
        }

        float r0 = NEG_INF, r1 = NEG_INF;
        #pragma unroll
        for (int nt = 0; nt < 8; nt++) {
            r0 = fmaxf(r0, fmaxf(s[nt][0], s[nt][1]));
            r1 = fmaxf(r1, fmaxf(s[nt][2], s[nt][3]));
        }
        r0 = fmaxf(r0, __shfl_xor_sync(0xffffffffu, r0, 1));
        r0 = fmaxf(r0, __shfl_xor_sync(0xffffffffu, r0, 2));
        r1 = fmaxf(r1, __shfl_xor_sync(0xffffffffu, r1, 1));
        r1 = fmaxf(r1, __shfl_xor_sync(0xffffffffu, r1, 2));

        float nm0 = fmaxf(m0, r0), nm1 = fmaxf(m1, r1);
        float a0 = __expf(m0 - nm0), a1 = __expf(m1 - nm1);
        float sum0 = 0.f, sum1 = 0.f;
        #pragma unroll
        for (int nt = 0; nt < 8; nt++) {
            s[nt][0] = __expf(s[nt][0] - nm0);
            s[nt][1] = __expf(s[nt][1] - nm0);
            s[nt][2] = __expf(s[nt][2] - nm1);
            s[nt][3] = __expf(s[nt][3] - nm1);
            sum0 += s[nt][0] + s[nt][1];
            sum1 += s[nt][2] + s[nt][3];
        }
        sum0 += __shfl_xor_sync(0xffffffffu, sum0, 1);
        sum0 += __shfl_xor_sync(0xffffffffu, sum0, 2);
        sum1 += __shfl_xor_sync(0xffffffffu, sum1, 1);
        sum1 += __shfl_xor_sync(0xffffffffu, sum1, 2);
        m0 = nm0; m1 = nm1;
        l0 = l0 * a0 + sum0;
        l1 = l1 * a1 + sum1;

        #pragma unroll
        for (int nt = 0; nt < 8; nt++) {
            o[nt][0] *= a0; o[nt][1] *= a0;
            o[nt][2] *= a1; o[nt][3] *= a1;
        }

        #pragma unroll
        for (int ks = 0; ks < 4; ks++) {
            uint32_t pa0 = f2h2(s[2 * ks][0],     s[2 * ks][1]);
            uint32_t pa1 = f2h2(s[2 * ks][2],     s[2 * ks][3]);
            uint32_t pa2 = f2h2(s[2 * ks + 1][0], s[2 * ks + 1][1]);
            uint32_t pa3 = f2h2(s[2 * ks + 1][2], s[2 * ks + 1][3]);
            #pragma unroll
            for (int ntp = 0; ntp < 4; ntp++) {
                uint32_t b0, b1, b2, b3;
                uint32_t addr = vstage + (uint32_t)(ks * 16 * KST32 + ntp * 8) * 4u;
                LDMATRIX_X4_TRANS(b0, b1, b2, b3, addr);
                mma_f16(o[2 * ntp][0],     o[2 * ntp][1],
                        o[2 * ntp][2],     o[2 * ntp][3],
                        pa0, pa1, pa2, pa3, b0, b1);
                mma_f16(o[2 * ntp + 1][0], o[2 * ntp + 1][1],
                        o[2 * ntp + 1][2], o[2 * ntp + 1][3],
                        pa0, pa1, pa2, pa3, b2, b3);
            }
        }
        __syncthreads();
    }

    float i0v = 1.f / l0, i1v = 1.f / l1;
    uint32_t* o0p = out + ((size_t)(bS + q0 + w * 16 + g) * Dz + h * HDz) / 2;
    uint32_t* o1p = o0p + (size_t)8 * Dz / 2;
    #pragma unroll
    for (int nt = 0; nt < 8; nt++) {
        int oidx = nt * 4 + tg;
        o0p[oidx] = f2h2(o[nt][0] * i0v, o[nt][1] * i0v);
        o1p[oidx] = f2h2(o[nt][2] * i1v, o[nt][3] * i1v);
    }
}

// ---------------------------------------------------------------------------
extern "C" void kernel_launch(void* const* d_in, const int* in_sizes, int n_in,
                              void* d_out, int out_size)
{
    const float* x      = (const float*)d_in[0];
    const float* w_qkv  = (const float*)d_in[1];
    const float* w_proj = (const float*)d_in[2];

    void *qkvp, *attnp, *xp, *wqp, *wpp;
    cudaGetSymbolAddress(&qkvp, g_qkv);
    cudaGetSymbolAddress(&attnp, g_attn);
    cudaGetSymbolAddress(&xp, g_x);
    cudaGetSymbolAddress(&wqp, g_wq);
    cudaGetSymbolAddress(&wpp, g_wp);

    cudaFuncSetAttribute(attn_mma_kernel,
                         cudaFuncAttributeMaxDynamicSharedMemorySize, ATT_SMEM);
    cudaFuncSetAttribute(gemm_mma_kernel,
                         cudaFuncAttributeMaxDynamicSharedMemorySize, GEMM_SMEM);

    const int M = Mz;

    // 0) fp16-convert all GEMM inputs (natural order)
    {
        int total = N16_X + N16_WQ + N16_WP;
        cvt_all_kernel<<<(total + 255) / 256, 256>>>(
            x, (uint32_t*)xp, w_qkv, (uint32_t*)wqp, w_proj, (uint32_t*)wpp);
    }

    // 1) QKV projection -> fp16 qkv (Q columns pre-scaled by 0.125)
    gemm_mma_kernel<<<dim3(D3z / 128, M / 128), 256, GEMM_SMEM>>>(
        (const uint32_t*)xp, (const uint32_t*)wqp, qkvp, M, D3z, Dz,
        1, 0.125f, Dz);

    // 2) Causal flash attention (all-fp16, ldmatrix everywhere)
    attn_mma_kernel<<<dim3(Sz / 64, Hz, Bz), 128, ATT_SMEM>>>(
        (const uint32_t*)qkvp, (uint32_t*)attnp);

    // 3) Output projection -> fp32 d_out
    gemm_mma_kernel<<<dim3(Dz / 128, M / 128), 256, GEMM_SMEM>>>(
        (const uint32_t*)attnp, (const uint32_t*)wpp, d_out, M, Dz, Dz,
        0, 1.0f, 0);
}